// round 4
// baseline (speedup 1.0000x reference)
#include <cuda_runtime.h>
#include <stdint.h>

// ---------------------------------------------------------------------------
// GCNConv on GB300 (sm_103a)
//   deg (with self loops) -> dinv = rsqrt(deg)
//   xlin = x @ W^T
//   acc  = bias + self-loop term + scatter-add over edges of xlin[src]*norm
//   out  = acc
// NOTE: edge_index is int32 on device (JAX x64 disabled downgrades jnp.int64).
// ---------------------------------------------------------------------------

#define NMAX 100000
#define DIM  128

// private scratch: static __device__ arrays (allocation-free per harness rules)
__device__ float g_deg[NMAX];
__device__ float g_dinv[NMAX];
__device__ float g_xlin[(size_t)NMAX * DIM];
__device__ float g_out [(size_t)NMAX * DIM];

// -------------------------------- degree ----------------------------------
__global__ void k_deg_init(int N) {
    int i = blockIdx.x * blockDim.x + threadIdx.x;
    if (i < N) g_deg[i] = 1.0f;  // self-loop
}

__global__ void k_deg_count(const int* __restrict__ ei, int E) {
    int e = blockIdx.x * blockDim.x + threadIdx.x;
    if (e < E) {
        int d = ei[E + e];  // dst row
        atomicAdd(&g_deg[d], 1.0f);
    }
}

__global__ void k_dinv(int N) {
    int i = blockIdx.x * blockDim.x + threadIdx.x;
    if (i < N) g_dinv[i] = rsqrtf(g_deg[i]);  // deg >= 1 (self loop)
}

// -------------------------------- GEMM -------------------------------------
// xlin[n][o] = sum_k x[n][k] * W[o][k]
// Block: 64 rows x 128 cols, 256 threads, per-thread 8M x 4N.
// K processed in 4 chunks of 32 with static smem (26 KB, no opt-in needed).
#define GEMM_BM 64

__global__ void k_gemm(const float* __restrict__ x, const float* __restrict__ W, int N) {
    __shared__ float xs[GEMM_BM][36];   // 64 rows x 32 k (+4 pad)
    __shared__ float ws[32][132];       // ws[kk][o] = W[o][kc*32+kk], padded row

    int t = threadIdx.x;
    int row0 = blockIdx.x * GEMM_BM;

    int tx = t & 31;        // 32 n-groups of 4 cols
    int ty = t >> 5;        // 8 m-groups of 8 rows
    int m0 = ty * 8, n0 = tx * 4;

    float acc[8][4];
#pragma unroll
    for (int mi = 0; mi < 8; mi++)
#pragma unroll
        for (int nj = 0; nj < 4; nj++) acc[mi][nj] = 0.f;

    for (int kc = 0; kc < 4; kc++) {
        // load x chunk: 64 rows x 8 float4 = 512 float4 (2 per thread)
        for (int i = t; i < GEMM_BM * 8; i += 256) {
            int r = i >> 3, c4 = i & 7;
            int gr = row0 + r;
            float4 v = (gr < N)
                ? reinterpret_cast<const float4*>(x)[(size_t)gr * 32 + kc * 8 + c4]
                : make_float4(0.f, 0.f, 0.f, 0.f);
            *reinterpret_cast<float4*>(&xs[r][c4 * 4]) = v;
        }
        // load W chunk transposed: 128 o x 32 kk (coalesced gmem reads)
        for (int i = t; i < DIM * 32; i += 256) {
            int o = i >> 5, kk = i & 31;
            ws[kk][o] = W[o * DIM + kc * 32 + kk];
        }
        __syncthreads();

#pragma unroll
        for (int k4 = 0; k4 < 8; k4++) {
            float wv[4][4];
#pragma unroll
            for (int kk = 0; kk < 4; kk++) {
                float4 w4 = *reinterpret_cast<const float4*>(&ws[k4 * 4 + kk][n0]);
                wv[kk][0] = w4.x; wv[kk][1] = w4.y; wv[kk][2] = w4.z; wv[kk][3] = w4.w;
            }
#pragma unroll
            for (int mi = 0; mi < 8; mi++) {
                float4 xv = *reinterpret_cast<const float4*>(&xs[m0 + mi][k4 * 4]);
#pragma unroll
                for (int nj = 0; nj < 4; nj++) {
                    acc[mi][nj] += xv.x * wv[0][nj];
                    acc[mi][nj] += xv.y * wv[1][nj];
                    acc[mi][nj] += xv.z * wv[2][nj];
                    acc[mi][nj] += xv.w * wv[3][nj];
                }
            }
        }
        __syncthreads();
    }

#pragma unroll
    for (int mi = 0; mi < 8; mi++) {
        int gr = row0 + m0 + mi;
        if (gr < N) {
            float4 v = make_float4(acc[mi][0], acc[mi][1], acc[mi][2], acc[mi][3]);
            *reinterpret_cast<float4*>(&g_xlin[(size_t)gr * DIM + n0]) = v;
        }
    }
}

// ---------------- acc init (bias + self loop), plain stores -----------------
__global__ void k_out_init(const float* __restrict__ b, int N) {
    int idx = blockIdx.x * blockDim.x + threadIdx.x;  // N*32 float4 slots
    if (idx >= N * 32) return;
    int i = idx >> 5, c4 = idx & 31;
    float di = g_dinv[i];
    float s = di * di;  // self-loop norm
    float4 v = reinterpret_cast<const float4*>(g_xlin)[idx];
    float4 bb = reinterpret_cast<const float4*>(b)[c4];
    v.x = v.x * s + bb.x;
    v.y = v.y * s + bb.y;
    v.z = v.z * s + bb.z;
    v.w = v.w * s + bb.w;
    reinterpret_cast<float4*>(g_out)[idx] = v;
}

// ------------------------------- edge scatter ------------------------------
// One warp per edge: gather xlin[src] (32 x float4), scale, atomicAdd into g_out[dst]
__global__ void k_scatter(const int* __restrict__ ei, int E) {
    int warp = (blockIdx.x * blockDim.x + threadIdx.x) >> 5;
    int lane = threadIdx.x & 31;
    if (warp >= E) return;

    int s = ei[warp];
    int d = ei[E + warp];
    float norm = g_dinv[s] * g_dinv[d];

    float4 v = reinterpret_cast<const float4*>(g_xlin)[(size_t)s * 32 + lane];

    float* p = g_out + (size_t)d * DIM + lane * 4;
    atomicAdd(p + 0, v.x * norm);
    atomicAdd(p + 1, v.y * norm);
    atomicAdd(p + 2, v.z * norm);
    atomicAdd(p + 3, v.w * norm);
}

// ------------------------------- final copy --------------------------------
__global__ void k_copy(float* __restrict__ out, int N) {
    int idx = blockIdx.x * blockDim.x + threadIdx.x;  // N*32 float4 slots
    if (idx < N * 32)
        reinterpret_cast<float4*>(out)[idx] = reinterpret_cast<const float4*>(g_out)[idx];
}

// ------------------------------- launcher ----------------------------------
extern "C" void kernel_launch(void* const* d_in, const int* in_sizes, int n_in,
                              void* d_out, int out_size) {
    const float* x  = (const float*)d_in[0];
    const int*   ei = (const int*)d_in[1];     // int32! (JAX x64 disabled)
    const float* W  = (const float*)d_in[2];
    const float* b  = (const float*)d_in[3];
    float*       out = (float*)d_out;

    int N = in_sizes[0] / DIM;   // 100000
    int E = in_sizes[1] / 2;     // 1600000

    const int T = 256;

    k_deg_init<<<(N + T - 1) / T, T>>>(N);
    k_deg_count<<<(E + T - 1) / T, T>>>(ei, E);
    k_dinv<<<(N + T - 1) / T, T>>>(N);

    k_gemm<<<(N + GEMM_BM - 1) / GEMM_BM, 256>>>(x, W, N);

    k_out_init<<<(N * 32 + T - 1) / T, T>>>(b, N);

    // warp per edge: E warps, 8 warps/block
    k_scatter<<<(E + 7) / 8, 256>>>(ei, E);

    k_copy<<<(N * 32 + T - 1) / T, T>>>(out, N);
}

// round 5
// speedup vs baseline: 2.4650x; 2.4650x over previous
#include <cuda_runtime.h>
#include <stdint.h>

// ---------------------------------------------------------------------------
// GCNConv on GB300 (sm_103a) — CSR counting-sort aggregation (no fp32 atomics)
//   1. histogram dst counts            (int atomics)
//   2. dinv = rsqrt(cnt+1)
//   3. exclusive scan -> row starts
//   4. bucket src indices by dst       (int cursor atomics)
//   5. xlin = x @ W^T                  (reg-blocked smem GEMM)
//   6. warp-per-dst gather+accumulate  (plain loads/stores only)
// edge_index is int32 on device (JAX x64 disabled).
// ---------------------------------------------------------------------------

#define NMAX 100000
#define EMAX 1600000
#define DIM  128
#define SCAN_BS 512
#define SCAN_BLOCKS ((NMAX + SCAN_BS - 1) / SCAN_BS)   // 196

__device__ int   g_cnt [NMAX];
__device__ int   g_start[NMAX];
__device__ int   g_cur [NMAX];
__device__ float g_dinv[NMAX];
__device__ int   g_bsum[SCAN_BLOCKS];
__device__ int   g_scantmp[NMAX];
__device__ int   g_esrc[EMAX];
__device__ float g_xlin[(size_t)NMAX * DIM];

// ----------------------------- histogram -----------------------------------
__global__ void k_zero(int N) {
    int i = blockIdx.x * blockDim.x + threadIdx.x;
    if (i < N) g_cnt[i] = 0;
}

__global__ void k_hist(const int* __restrict__ ei, int E) {
    int e = blockIdx.x * blockDim.x + threadIdx.x;
    if (e < E) atomicAdd(&g_cnt[ei[E + e]], 1);
}

__global__ void k_dinv(int N) {
    int i = blockIdx.x * blockDim.x + threadIdx.x;
    if (i < N) g_dinv[i] = rsqrtf((float)(g_cnt[i] + 1));  // +1 self-loop
}

// ----------------------------- 3-pass scan ----------------------------------
__global__ void k_scan1(int N) {
    __shared__ int sm[SCAN_BS];
    int i = blockIdx.x * SCAN_BS + threadIdx.x;
    int v = (i < N) ? g_cnt[i] : 0;
    sm[threadIdx.x] = v;
    __syncthreads();
#pragma unroll
    for (int ofs = 1; ofs < SCAN_BS; ofs <<= 1) {
        int t = (threadIdx.x >= ofs) ? sm[threadIdx.x - ofs] : 0;
        __syncthreads();
        sm[threadIdx.x] += t;
        __syncthreads();
    }
    if (i < N) g_scantmp[i] = sm[threadIdx.x] - v;          // exclusive in-block
    if (threadIdx.x == SCAN_BS - 1) g_bsum[blockIdx.x] = sm[threadIdx.x];
}

__global__ void k_scan2() {  // single block, 256 >= SCAN_BLOCKS
    __shared__ int sm[256];
    int v = (threadIdx.x < SCAN_BLOCKS) ? g_bsum[threadIdx.x] : 0;
    sm[threadIdx.x] = v;
    __syncthreads();
#pragma unroll
    for (int ofs = 1; ofs < 256; ofs <<= 1) {
        int t = (threadIdx.x >= ofs) ? sm[threadIdx.x - ofs] : 0;
        __syncthreads();
        sm[threadIdx.x] += t;
        __syncthreads();
    }
    if (threadIdx.x < SCAN_BLOCKS) g_bsum[threadIdx.x] = sm[threadIdx.x] - v;
}

__global__ void k_scan3(int N) {
    int i = blockIdx.x * blockDim.x + threadIdx.x;
    if (i < N) {
        int s = g_scantmp[i] + g_bsum[i / SCAN_BS];
        g_start[i] = s;
        g_cur[i] = s;
    }
}

// ----------------------------- bucket edges ---------------------------------
__global__ void k_bucket(const int* __restrict__ ei, int E) {
    int e = blockIdx.x * blockDim.x + threadIdx.x;
    if (e < E) {
        int s = ei[e];
        int d = ei[E + e];
        int pos = atomicAdd(&g_cur[d], 1);
        g_esrc[pos] = s;
    }
}

// -------------------------------- GEMM --------------------------------------
#define GEMM_BM 64

__global__ void k_gemm(const float* __restrict__ x, const float* __restrict__ W, int N) {
    __shared__ float xs[GEMM_BM][36];
    __shared__ float ws[32][132];

    int t = threadIdx.x;
    int row0 = blockIdx.x * GEMM_BM;
    int tx = t & 31, ty = t >> 5;
    int m0 = ty * 8, n0 = tx * 4;

    float acc[8][4];
#pragma unroll
    for (int mi = 0; mi < 8; mi++)
#pragma unroll
        for (int nj = 0; nj < 4; nj++) acc[mi][nj] = 0.f;

    for (int kc = 0; kc < 4; kc++) {
        for (int i = t; i < GEMM_BM * 8; i += 256) {
            int r = i >> 3, c4 = i & 7;
            int gr = row0 + r;
            float4 v = (gr < N)
                ? reinterpret_cast<const float4*>(x)[(size_t)gr * 32 + kc * 8 + c4]
                : make_float4(0.f, 0.f, 0.f, 0.f);
            *reinterpret_cast<float4*>(&xs[r][c4 * 4]) = v;
        }
        for (int i = t; i < DIM * 32; i += 256) {
            int o = i >> 5, kk = i & 31;
            ws[kk][o] = W[o * DIM + kc * 32 + kk];
        }
        __syncthreads();

#pragma unroll
        for (int k4 = 0; k4 < 8; k4++) {
            float wv[4][4];
#pragma unroll
            for (int kk = 0; kk < 4; kk++) {
                float4 w4 = *reinterpret_cast<const float4*>(&ws[k4 * 4 + kk][n0]);
                wv[kk][0] = w4.x; wv[kk][1] = w4.y; wv[kk][2] = w4.z; wv[kk][3] = w4.w;
            }
#pragma unroll
            for (int mi = 0; mi < 8; mi++) {
                float4 xv = *reinterpret_cast<const float4*>(&xs[m0 + mi][k4 * 4]);
#pragma unroll
                for (int nj = 0; nj < 4; nj++) {
                    acc[mi][nj] += xv.x * wv[0][nj];
                    acc[mi][nj] += xv.y * wv[1][nj];
                    acc[mi][nj] += xv.z * wv[2][nj];
                    acc[mi][nj] += xv.w * wv[3][nj];
                }
            }
        }
        __syncthreads();
    }

#pragma unroll
    for (int mi = 0; mi < 8; mi++) {
        int gr = row0 + m0 + mi;
        if (gr < N) {
            float4 v = make_float4(acc[mi][0], acc[mi][1], acc[mi][2], acc[mi][3]);
            *reinterpret_cast<float4*>(&g_xlin[(size_t)gr * DIM + n0]) = v;
        }
    }
}

// ------------------------- gather + accumulate -------------------------------
// One warp per dst node. acc covers 4 cols per lane (128 total).
__global__ void k_accum(const float* __restrict__ b, float* __restrict__ out, int N) {
    int d = blockIdx.x * 8 + (threadIdx.x >> 5);
    int lane = threadIdx.x & 31;
    if (d >= N) return;

    float dd = g_dinv[d];
    int start = g_start[d];
    int cnt = g_cnt[d];

    const float4* xlin4 = reinterpret_cast<const float4*>(g_xlin);

    // bias + self loop
    float4 bb = reinterpret_cast<const float4*>(b)[lane];
    float4 sv = xlin4[(size_t)d * 32 + lane];
    float s2 = dd * dd;
    float4 acc;
    acc.x = bb.x + sv.x * s2;
    acc.y = bb.y + sv.y * s2;
    acc.z = bb.z + sv.z * s2;
    acc.w = bb.w + sv.w * s2;

    for (int base = 0; base < cnt; base += 32) {
        int k = base + lane;
        int s = (k < cnt) ? g_esrc[start + k] : 0;
        float nm = (k < cnt) ? g_dinv[s] * dd : 0.f;
        int m = min(32, cnt - base);
        for (int j = 0; j < m; j++) {
            int sj = __shfl_sync(0xffffffffu, s, j);
            float nj = __shfl_sync(0xffffffffu, nm, j);
            float4 v = xlin4[(size_t)sj * 32 + lane];
            acc.x += v.x * nj;
            acc.y += v.y * nj;
            acc.z += v.z * nj;
            acc.w += v.w * nj;
        }
    }

    reinterpret_cast<float4*>(out)[(size_t)d * 32 + lane] = acc;
}

// ------------------------------- launcher ------------------------------------
extern "C" void kernel_launch(void* const* d_in, const int* in_sizes, int n_in,
                              void* d_out, int out_size) {
    const float* x  = (const float*)d_in[0];
    const int*   ei = (const int*)d_in[1];   // int32 (JAX x64 disabled)
    const float* W  = (const float*)d_in[2];
    const float* b  = (const float*)d_in[3];
    float*       out = (float*)d_out;

    int N = in_sizes[0] / DIM;   // 100000
    int E = in_sizes[1] / 2;     // 1600000

    const int T = 256;

    k_zero<<<(N + T - 1) / T, T>>>(N);
    k_hist<<<(E + T - 1) / T, T>>>(ei, E);
    k_dinv<<<(N + T - 1) / T, T>>>(N);

    k_scan1<<<SCAN_BLOCKS, SCAN_BS>>>(N);
    k_scan2<<<1, 256>>>();
    k_scan3<<<(N + T - 1) / T, T>>>(N);

    k_bucket<<<(E + T - 1) / T, T>>>(ei, E);

    k_gemm<<<(N + GEMM_BM - 1) / GEMM_BM, 256>>>(x, W, N);

    k_accum<<<(N + 7) / 8, 256>>>(b, out, N);
}

// round 7
// speedup vs baseline: 2.8714x; 1.1649x over previous
#include <cuda_runtime.h>
#include <stdint.h>

// ---------------------------------------------------------------------------
// GCNConv on GB300 (sm_103a, compute_103 PTX target -> no tcgen05; use
// family-compatible mma.sync tf32x3 for the GEMM)
//   CSR counting-sort aggregation (no fp32 atomics) + mma.sync TF32x3 GEMM
// edge_index is int32 on device (JAX x64 disabled).
// ---------------------------------------------------------------------------

#define NMAX 100000
#define EMAX 1600000
#define DIM  128
#define SCAN_BS 512
#define SCAN_BLOCKS ((NMAX + SCAN_BS - 1) / SCAN_BS)   // 196

__device__ int   g_cnt [NMAX];
__device__ int   g_start[NMAX];
__device__ int   g_cur [NMAX];
__device__ float g_dinv[NMAX];
__device__ int   g_bsum[SCAN_BLOCKS];
__device__ int   g_scantmp[NMAX];
__device__ int   g_esrc[EMAX];
__device__ float g_xlin[(size_t)NMAX * DIM];

// ----------------------------- histogram -----------------------------------
__global__ void k_zero(int N) {
    int i = blockIdx.x * blockDim.x + threadIdx.x;
    if (i < N) g_cnt[i] = 0;
}
__global__ void k_hist(const int* __restrict__ ei, int E) {
    int e = blockIdx.x * blockDim.x + threadIdx.x;
    if (e < E) atomicAdd(&g_cnt[ei[E + e]], 1);
}
__global__ void k_dinv(int N) {
    int i = blockIdx.x * blockDim.x + threadIdx.x;
    if (i < N) g_dinv[i] = rsqrtf((float)(g_cnt[i] + 1));
}

// ----------------------------- 3-pass scan ----------------------------------
__global__ void k_scan1(int N) {
    __shared__ int sm[SCAN_BS];
    int i = blockIdx.x * SCAN_BS + threadIdx.x;
    int v = (i < N) ? g_cnt[i] : 0;
    sm[threadIdx.x] = v;
    __syncthreads();
#pragma unroll
    for (int ofs = 1; ofs < SCAN_BS; ofs <<= 1) {
        int t = (threadIdx.x >= ofs) ? sm[threadIdx.x - ofs] : 0;
        __syncthreads();
        sm[threadIdx.x] += t;
        __syncthreads();
    }
    if (i < N) g_scantmp[i] = sm[threadIdx.x] - v;
    if (threadIdx.x == SCAN_BS - 1) g_bsum[blockIdx.x] = sm[threadIdx.x];
}
__global__ void k_scan2() {
    __shared__ int sm[256];
    int v = (threadIdx.x < SCAN_BLOCKS) ? g_bsum[threadIdx.x] : 0;
    sm[threadIdx.x] = v;
    __syncthreads();
#pragma unroll
    for (int ofs = 1; ofs < 256; ofs <<= 1) {
        int t = (threadIdx.x >= ofs) ? sm[threadIdx.x - ofs] : 0;
        __syncthreads();
        sm[threadIdx.x] += t;
        __syncthreads();
    }
    if (threadIdx.x < SCAN_BLOCKS) g_bsum[threadIdx.x] = sm[threadIdx.x] - v;
}
__global__ void k_scan3(int N) {
    int i = blockIdx.x * blockDim.x + threadIdx.x;
    if (i < N) {
        int s = g_scantmp[i] + g_bsum[i / SCAN_BS];
        g_start[i] = s;
        g_cur[i] = s;
    }
}
__global__ void k_bucket(const int* __restrict__ ei, int E) {
    int e = blockIdx.x * blockDim.x + threadIdx.x;
    if (e < E) {
        int s = ei[e];
        int d = ei[E + e];
        g_esrc[atomicAdd(&g_cur[d], 1)] = s;
    }
}

// ------------------------- mma.sync TF32x3 GEMM ------------------------------
// xlin[n][o] = sum_k x[n][k] * W[o][k]
// CTA: 128 rows x 128 cols; 8 warps = 4 row-groups(32) x 2 col-groups(64);
// per warp 2 m16-tiles x 8 n8-tiles. K in 4 chunks of 32, smem hi/lo staging.

#define PAD_A 36     // bank = 4*tg + tq -> conflict free
#define PAD_W 136    // bank = 8*tq + tg -> conflict free
#define XS_HI 0
#define XS_LO (128 * PAD_A)
#define WS_HI (2 * 128 * PAD_A)
#define WS_LO (2 * 128 * PAD_A + 32 * PAD_W)
#define SM_FLOATS (2 * 128 * PAD_A + 2 * 32 * PAD_W)   // 17920 floats = 71680 B

__device__ __forceinline__ float tf32_rna(float v) {
    uint32_t r;
    asm("cvt.rna.tf32.f32 %0, %1;" : "=r"(r) : "f"(v));
    return __uint_as_float(r);
}

__device__ __forceinline__ void mma_tf32(float c[4], uint32_t a0, uint32_t a1,
                                         uint32_t a2, uint32_t a3,
                                         uint32_t b0, uint32_t b1) {
    asm volatile(
        "mma.sync.aligned.m16n8k8.row.col.f32.tf32.tf32.f32 "
        "{%0,%1,%2,%3}, {%4,%5,%6,%7}, {%8,%9}, {%0,%1,%2,%3};"
        : "+f"(c[0]), "+f"(c[1]), "+f"(c[2]), "+f"(c[3])
        : "r"(a0), "r"(a1), "r"(a2), "r"(a3), "r"(b0), "r"(b1));
}

__global__ void __launch_bounds__(256) k_gemm_mma(const float* __restrict__ x,
                                                  const float* __restrict__ W, int N) {
    extern __shared__ float sm[];
    int t = threadIdx.x;
    int lane = t & 31, w = t >> 5;
    int tg = lane >> 2, tq = lane & 3;
    int mwarp = (w >> 1) * 32;   // 0,32,64,96
    int nwarp = (w & 1) * 64;    // 0,64
    int row0 = blockIdx.x * 128;

    const float4* x4 = reinterpret_cast<const float4*>(x);
    const float4* W4 = reinterpret_cast<const float4*>(W);

    float acc[2][8][4];
#pragma unroll
    for (int mt = 0; mt < 2; mt++)
#pragma unroll
        for (int nt = 0; nt < 8; nt++)
#pragma unroll
            for (int c = 0; c < 4; c++) acc[mt][nt][c] = 0.f;

    for (int kc = 0; kc < 4; kc++) {
        // stage x chunk: 128 rows x 32 k (as hi/lo), float4 path
        for (int i = t; i < 1024; i += 256) {
            int r = i >> 3, q = i & 7;
            int gr = row0 + r;
            float4 v = (gr < N) ? x4[(size_t)gr * 32 + kc * 8 + q]
                                : make_float4(0.f, 0.f, 0.f, 0.f);
            float4 hi, lo;
            hi.x = tf32_rna(v.x); lo.x = v.x - hi.x;
            hi.y = tf32_rna(v.y); lo.y = v.y - hi.y;
            hi.z = tf32_rna(v.z); lo.z = v.z - hi.z;
            hi.w = tf32_rna(v.w); lo.w = v.w - hi.w;
            *reinterpret_cast<float4*>(&sm[XS_HI + r * PAD_A + q * 4]) = hi;
            *reinterpret_cast<float4*>(&sm[XS_LO + r * PAD_A + q * 4]) = lo;
        }
        // stage W chunk transposed: ws[k][o] = W[o][kc*32+k] (as hi/lo)
        for (int i = t; i < 1024; i += 256) {
            int o = i & 127, q = i >> 7;           // q: 0..7 -> k = 4q..4q+3
            float4 v = W4[(size_t)o * 32 + kc * 8 + q];
            float f[4] = {v.x, v.y, v.z, v.w};
#pragma unroll
            for (int j = 0; j < 4; j++) {
                float hi = tf32_rna(f[j]);
                sm[WS_HI + (q * 4 + j) * PAD_W + o] = hi;
                sm[WS_LO + (q * 4 + j) * PAD_W + o] = f[j] - hi;
            }
        }
        __syncthreads();

#pragma unroll
        for (int ks = 0; ks < 4; ks++) {
            int kb = ks * 8;
            uint32_t ahi[2][4], alo[2][4];
#pragma unroll
            for (int mt = 0; mt < 2; mt++) {
                int mrow = mwarp + mt * 16 + tg;
                ahi[mt][0] = __float_as_uint(sm[XS_HI + (mrow    ) * PAD_A + kb + tq]);
                ahi[mt][1] = __float_as_uint(sm[XS_HI + (mrow + 8) * PAD_A + kb + tq]);
                ahi[mt][2] = __float_as_uint(sm[XS_HI + (mrow    ) * PAD_A + kb + tq + 4]);
                ahi[mt][3] = __float_as_uint(sm[XS_HI + (mrow + 8) * PAD_A + kb + tq + 4]);
                alo[mt][0] = __float_as_uint(sm[XS_LO + (mrow    ) * PAD_A + kb + tq]);
                alo[mt][1] = __float_as_uint(sm[XS_LO + (mrow + 8) * PAD_A + kb + tq]);
                alo[mt][2] = __float_as_uint(sm[XS_LO + (mrow    ) * PAD_A + kb + tq + 4]);
                alo[mt][3] = __float_as_uint(sm[XS_LO + (mrow + 8) * PAD_A + kb + tq + 4]);
            }
#pragma unroll
            for (int nt = 0; nt < 8; nt++) {
                int o = nwarp + nt * 8 + tg;
                uint32_t bhi0 = __float_as_uint(sm[WS_HI + (kb + tq    ) * PAD_W + o]);
                uint32_t bhi1 = __float_as_uint(sm[WS_HI + (kb + tq + 4) * PAD_W + o]);
                uint32_t blo0 = __float_as_uint(sm[WS_LO + (kb + tq    ) * PAD_W + o]);
                uint32_t blo1 = __float_as_uint(sm[WS_LO + (kb + tq + 4) * PAD_W + o]);
#pragma unroll
                for (int mt = 0; mt < 2; mt++) {
                    mma_tf32(acc[mt][nt], ahi[mt][0], ahi[mt][1], ahi[mt][2], ahi[mt][3], bhi0, bhi1);
                    mma_tf32(acc[mt][nt], ahi[mt][0], ahi[mt][1], ahi[mt][2], ahi[mt][3], blo0, blo1);
                    mma_tf32(acc[mt][nt], alo[mt][0], alo[mt][1], alo[mt][2], alo[mt][3], bhi0, bhi1);
                }
            }
        }
        __syncthreads();
    }

    // epilogue: c0,c1 -> (row, 2 cols), c2,c3 -> (row+8, 2 cols); float2 stores
#pragma unroll
    for (int mt = 0; mt < 2; mt++) {
        int gr = row0 + mwarp + mt * 16 + tg;
#pragma unroll
        for (int nt = 0; nt < 8; nt++) {
            int gc = nwarp + nt * 8 + tq * 2;
            if (gr < N)
                *reinterpret_cast<float2*>(&g_xlin[(size_t)gr * DIM + gc]) =
                    make_float2(acc[mt][nt][0], acc[mt][nt][1]);
            if (gr + 8 < N)
                *reinterpret_cast<float2*>(&g_xlin[(size_t)(gr + 8) * DIM + gc]) =
                    make_float2(acc[mt][nt][2], acc[mt][nt][3]);
        }
    }
}

// ------------------------- gather + accumulate -------------------------------
__global__ void k_accum(const float* __restrict__ b, float* __restrict__ out, int N) {
    int d = blockIdx.x * 8 + (threadIdx.x >> 5);
    int lane = threadIdx.x & 31;
    if (d >= N) return;

    float dd = g_dinv[d];
    int start = g_start[d];
    int cnt = g_cnt[d];

    const float4* xlin4 = reinterpret_cast<const float4*>(g_xlin);

    float4 bb = reinterpret_cast<const float4*>(b)[lane];
    float4 sv = xlin4[(size_t)d * 32 + lane];
    float s2 = dd * dd;
    float4 acc;
    acc.x = bb.x + sv.x * s2;
    acc.y = bb.y + sv.y * s2;
    acc.z = bb.z + sv.z * s2;
    acc.w = bb.w + sv.w * s2;

    for (int base = 0; base < cnt; base += 32) {
        int k = base + lane;
        int s = (k < cnt) ? g_esrc[start + k] : 0;
        float nm = (k < cnt) ? g_dinv[s] * dd : 0.f;
        int m = min(32, cnt - base);
        for (int j = 0; j < m; j++) {
            int sj = __shfl_sync(0xffffffffu, s, j);
            float nj = __shfl_sync(0xffffffffu, nm, j);
            float4 v = xlin4[(size_t)sj * 32 + lane];
            acc.x += v.x * nj;
            acc.y += v.y * nj;
            acc.z += v.z * nj;
            acc.w += v.w * nj;
        }
    }

    reinterpret_cast<float4*>(out)[(size_t)d * 32 + lane] = acc;
}

// ------------------------------- launcher ------------------------------------
extern "C" void kernel_launch(void* const* d_in, const int* in_sizes, int n_in,
                              void* d_out, int out_size) {
    const float* x  = (const float*)d_in[0];
    const int*   ei = (const int*)d_in[1];   // int32 (JAX x64 disabled)
    const float* W  = (const float*)d_in[2];
    const float* b  = (const float*)d_in[3];
    float*       out = (float*)d_out;

    int N = in_sizes[0] / DIM;   // 100000
    int E = in_sizes[1] / 2;     // 1600000

    const int T = 256;

    k_zero<<<(N + T - 1) / T, T>>>(N);
    k_hist<<<(E + T - 1) / T, T>>>(ei, E);
    k_dinv<<<(N + T - 1) / T, T>>>(N);

    k_scan1<<<SCAN_BLOCKS, SCAN_BS>>>(N);
    k_scan2<<<1, 256>>>();
    k_scan3<<<(N + T - 1) / T, T>>>(N);

    k_bucket<<<(E + T - 1) / T, T>>>(ei, E);

    int smem_bytes = SM_FLOATS * sizeof(float);   // 71680
    cudaFuncSetAttribute(k_gemm_mma, cudaFuncAttributeMaxDynamicSharedMemorySize, smem_bytes);
    k_gemm_mma<<<(N + 127) / 128, 256, smem_bytes>>>(x, W, N);

    k_accum<<<(N + 7) / 8, 256>>>(b, out, N);
}

// round 8
// speedup vs baseline: 3.2103x; 1.1180x over previous
#include <cuda_runtime.h>
#include <stdint.h>

// ---------------------------------------------------------------------------
// GCNConv on GB300 (sm_103a, compute_103 PTX target -> mma.sync tf32x3 GEMM)
//   CSR counting-sort aggregation (no fp32 atomics), GEMM overlapped with
//   CSR build on a second stream (fork/join events, capture-legal).
// edge_index is int32 on device (JAX x64 disabled).
// ---------------------------------------------------------------------------

#define NMAX 100000
#define EMAX 1600000
#define DIM  128
#define SCAN_BS 512
#define SCAN_BLOCKS ((NMAX + SCAN_BS - 1) / SCAN_BS)   // 196

__device__ int   g_cnt [NMAX];
__device__ int   g_start[NMAX];
__device__ int   g_cur [NMAX];
__device__ float g_dinv[NMAX];
__device__ int   g_bsum[SCAN_BLOCKS];
__device__ int   g_scantmp[NMAX];
__device__ int   g_esrc[EMAX];
__device__ float g_xlin[(size_t)NMAX * DIM];

// ----------------------------- histogram -----------------------------------
__global__ void k_zero(int N) {
    int i = blockIdx.x * blockDim.x + threadIdx.x;
    if (i < N) g_cnt[i] = 0;
}
__global__ void k_hist(const int* __restrict__ ei, int E) {
    int e = blockIdx.x * blockDim.x + threadIdx.x;
    if (e < E) atomicAdd(&g_cnt[ei[E + e]], 1);
}

// ------------------------- 3-pass scan (+dinv fused) -------------------------
__global__ void k_scan1(int N) {
    __shared__ int sm[SCAN_BS];
    int i = blockIdx.x * SCAN_BS + threadIdx.x;
    int v = (i < N) ? g_cnt[i] : 0;
    if (i < N) g_dinv[i] = rsqrtf((float)(v + 1));   // fused dinv
    sm[threadIdx.x] = v;
    __syncthreads();
#pragma unroll
    for (int ofs = 1; ofs < SCAN_BS; ofs <<= 1) {
        int t = (threadIdx.x >= ofs) ? sm[threadIdx.x - ofs] : 0;
        __syncthreads();
        sm[threadIdx.x] += t;
        __syncthreads();
    }
    if (i < N) g_scantmp[i] = sm[threadIdx.x] - v;
    if (threadIdx.x == SCAN_BS - 1) g_bsum[blockIdx.x] = sm[threadIdx.x];
}
__global__ void k_scan2() {
    __shared__ int sm[256];
    int v = (threadIdx.x < SCAN_BLOCKS) ? g_bsum[threadIdx.x] : 0;
    sm[threadIdx.x] = v;
    __syncthreads();
#pragma unroll
    for (int ofs = 1; ofs < 256; ofs <<= 1) {
        int t = (threadIdx.x >= ofs) ? sm[threadIdx.x - ofs] : 0;
        __syncthreads();
        sm[threadIdx.x] += t;
        __syncthreads();
    }
    if (threadIdx.x < SCAN_BLOCKS) g_bsum[threadIdx.x] = sm[threadIdx.x] - v;
}
__global__ void k_scan3(int N) {
    int i = blockIdx.x * blockDim.x + threadIdx.x;
    if (i < N) {
        int s = g_scantmp[i] + g_bsum[i / SCAN_BS];
        g_start[i] = s;
        g_cur[i] = s;
    }
}
__global__ void k_bucket(const int* __restrict__ ei, int E) {
    int e = blockIdx.x * blockDim.x + threadIdx.x;
    if (e < E) {
        int s = ei[e];
        int d = ei[E + e];
        g_esrc[atomicAdd(&g_cur[d], 1)] = s;
    }
}

// ------------------------- mma.sync TF32x3 GEMM ------------------------------
// xlin[n][o] = sum_k x[n][k] * W[o][k]
// CTA: 128 rows x 128 cols; 8 warps = 4 row-groups(32) x 2 col-groups(64).
// K in 2 chunks of 64; raw f32 staged in smem; hi/lo tf32 split in registers.

#define PA 68      // xs row pitch: bank = 4*tg + tq -> conflict free
#define PW 136     // ws row pitch: bank = 8*tq + tg -> conflict free
#define XS 0                       // 128*68 = 8704 floats
#define WS (128 * PA)              // 64*136 = 8704 floats
#define SM_FLOATS (128 * PA + 64 * PW)   // 17408 floats = 69632 B

__device__ __forceinline__ float tf32_rna(float v) {
    uint32_t r;
    asm("cvt.rna.tf32.f32 %0, %1;" : "=r"(r) : "f"(v));
    return __uint_as_float(r);
}

__device__ __forceinline__ void mma_tf32(float c[4], uint32_t a0, uint32_t a1,
                                         uint32_t a2, uint32_t a3,
                                         uint32_t b0, uint32_t b1) {
    asm volatile(
        "mma.sync.aligned.m16n8k8.row.col.f32.tf32.tf32.f32 "
        "{%0,%1,%2,%3}, {%4,%5,%6,%7}, {%8,%9}, {%0,%1,%2,%3};"
        : "+f"(c[0]), "+f"(c[1]), "+f"(c[2]), "+f"(c[3])
        : "r"(a0), "r"(a1), "r"(a2), "r"(a3), "r"(b0), "r"(b1));
}

__global__ void __launch_bounds__(256) k_gemm_mma(const float* __restrict__ x,
                                                  const float* __restrict__ W, int N) {
    extern __shared__ float sm[];
    int t = threadIdx.x;
    int lane = t & 31, w = t >> 5;
    int tg = lane >> 2, tq = lane & 3;
    int mwarp = (w >> 1) * 32;   // 0,32,64,96
    int nwarp = (w & 1) * 64;    // 0,64
    int row0 = blockIdx.x * 128;

    const float4* x4 = reinterpret_cast<const float4*>(x);
    const float4* W4 = reinterpret_cast<const float4*>(W);

    float acc[2][8][4];
#pragma unroll
    for (int mt = 0; mt < 2; mt++)
#pragma unroll
        for (int nt = 0; nt < 8; nt++)
#pragma unroll
            for (int c = 0; c < 4; c++) acc[mt][nt][c] = 0.f;

    for (int kc = 0; kc < 2; kc++) {
        // stage x chunk raw: 128 rows x 64 k = 2048 float4 (8/thread)
        for (int i = t; i < 2048; i += 256) {
            int r = i >> 4, q = i & 15;
            int gr = row0 + r;
            float4 v = (gr < N) ? x4[(size_t)gr * 32 + kc * 16 + q]
                                : make_float4(0.f, 0.f, 0.f, 0.f);
            *reinterpret_cast<float4*>(&sm[XS + r * PA + q * 4]) = v;
        }
        // stage W chunk transposed raw: ws[k][o] = W[o][kc*64+k]
        for (int i = t; i < 2048; i += 256) {
            int o = i & 127, q = i >> 7;      // q: 0..15 -> k = 4q..4q+3
            float4 v = W4[(size_t)o * 32 + kc * 16 + q];
            sm[WS + (q * 4 + 0) * PW + o] = v.x;
            sm[WS + (q * 4 + 1) * PW + o] = v.y;
            sm[WS + (q * 4 + 2) * PW + o] = v.z;
            sm[WS + (q * 4 + 3) * PW + o] = v.w;
        }
        __syncthreads();

#pragma unroll
        for (int ks = 0; ks < 8; ks++) {
            int kb = ks * 8;
            uint32_t ahi[2][4], alo[2][4];
#pragma unroll
            for (int mt = 0; mt < 2; mt++) {
                int mrow = mwarp + mt * 16 + tg;
                float ar[4];
                ar[0] = sm[XS + (mrow    ) * PA + kb + tq];
                ar[1] = sm[XS + (mrow + 8) * PA + kb + tq];
                ar[2] = sm[XS + (mrow    ) * PA + kb + tq + 4];
                ar[3] = sm[XS + (mrow + 8) * PA + kb + tq + 4];
#pragma unroll
                for (int j = 0; j < 4; j++) {
                    float hi = tf32_rna(ar[j]);
                    ahi[mt][j] = __float_as_uint(hi);
                    alo[mt][j] = __float_as_uint(ar[j] - hi);
                }
            }
#pragma unroll
            for (int nt = 0; nt < 8; nt++) {
                int o = nwarp + nt * 8 + tg;
                float b0r = sm[WS + (kb + tq    ) * PW + o];
                float b1r = sm[WS + (kb + tq + 4) * PW + o];
                float bh0 = tf32_rna(b0r), bh1 = tf32_rna(b1r);
                uint32_t bhi0 = __float_as_uint(bh0);
                uint32_t bhi1 = __float_as_uint(bh1);
                uint32_t blo0 = __float_as_uint(b0r - bh0);
                uint32_t blo1 = __float_as_uint(b1r - bh1);
#pragma unroll
                for (int mt = 0; mt < 2; mt++) {
                    mma_tf32(acc[mt][nt], ahi[mt][0], ahi[mt][1], ahi[mt][2], ahi[mt][3], bhi0, bhi1);
                    mma_tf32(acc[mt][nt], ahi[mt][0], ahi[mt][1], ahi[mt][2], ahi[mt][3], blo0, blo1);
                    mma_tf32(acc[mt][nt], alo[mt][0], alo[mt][1], alo[mt][2], alo[mt][3], bhi0, bhi1);
                }
            }
        }
        __syncthreads();
    }

    // epilogue: float2 stores
#pragma unroll
    for (int mt = 0; mt < 2; mt++) {
        int gr = row0 + mwarp + mt * 16 + tg;
#pragma unroll
        for (int nt = 0; nt < 8; nt++) {
            int gc = nwarp + nt * 8 + tq * 2;
            if (gr < N)
                *reinterpret_cast<float2*>(&g_xlin[(size_t)gr * DIM + gc]) =
                    make_float2(acc[mt][nt][0], acc[mt][nt][1]);
            if (gr + 8 < N)
                *reinterpret_cast<float2*>(&g_xlin[(size_t)(gr + 8) * DIM + gc]) =
                    make_float2(acc[mt][nt][2], acc[mt][nt][3]);
        }
    }
}

// ------------------------- gather + accumulate -------------------------------
__global__ void k_accum(const float* __restrict__ b, float* __restrict__ out, int N) {
    int d = blockIdx.x * 8 + (threadIdx.x >> 5);
    int lane = threadIdx.x & 31;
    if (d >= N) return;

    float dd = g_dinv[d];
    int start = g_start[d];
    int cnt = g_cnt[d];

    const float4* xlin4 = reinterpret_cast<const float4*>(g_xlin);

    float4 bb = reinterpret_cast<const float4*>(b)[lane];
    float4 sv = xlin4[(size_t)d * 32 + lane];
    float s2 = dd * dd;
    float4 acc;
    acc.x = bb.x + sv.x * s2;
    acc.y = bb.y + sv.y * s2;
    acc.z = bb.z + sv.z * s2;
    acc.w = bb.w + sv.w * s2;

    for (int base = 0; base < cnt; base += 32) {
        int k = base + lane;
        int s = (k < cnt) ? g_esrc[start + k] : 0;
        float nm = (k < cnt) ? g_dinv[s] * dd : 0.f;
        int m = min(32, cnt - base);
        for (int j = 0; j < m; j++) {
            int sj = __shfl_sync(0xffffffffu, s, j);
            float nj = __shfl_sync(0xffffffffu, nm, j);
            float4 v = xlin4[(size_t)sj * 32 + lane];
            acc.x += v.x * nj;
            acc.y += v.y * nj;
            acc.z += v.z * nj;
            acc.w += v.w * nj;
        }
    }

    reinterpret_cast<float4*>(out)[(size_t)d * 32 + lane] = acc;
}

// ------------------------------- launcher ------------------------------------
extern "C" void kernel_launch(void* const* d_in, const int* in_sizes, int n_in,
                              void* d_out, int out_size) {
    const float* x  = (const float*)d_in[0];
    const int*   ei = (const int*)d_in[1];   // int32 (JAX x64 disabled)
    const float* W  = (const float*)d_in[2];
    const float* b  = (const float*)d_in[3];
    float*       out = (float*)d_out;

    int N = in_sizes[0] / DIM;   // 100000
    int E = in_sizes[1] / 2;     // 1600000

    // one-time stream/event setup (host-side infra; happens on the first,
    // non-captured correctness call — does not change per-call work)
    static cudaStream_t s2 = 0;
    static cudaEvent_t ev_fork = 0, ev_join = 0;
    static bool init_done = false;
    if (!init_done) {
        if (cudaStreamCreateWithFlags(&s2, cudaStreamNonBlocking) != cudaSuccess) s2 = 0;
        cudaEventCreateWithFlags(&ev_fork, cudaEventDisableTiming);
        cudaEventCreateWithFlags(&ev_join, cudaEventDisableTiming);
        init_done = true;
    }

    const int T = 256;
    int smem_bytes = SM_FLOATS * sizeof(float);   // 69632
    cudaFuncSetAttribute(k_gemm_mma, cudaFuncAttributeMaxDynamicSharedMemorySize, smem_bytes);

    bool fork = (s2 != 0) && ev_fork && ev_join;

    if (fork) {
        // fork GEMM onto s2, overlapped with CSR build on stream 0
        cudaEventRecord(ev_fork, 0);
        cudaStreamWaitEvent(s2, ev_fork, 0);
        k_gemm_mma<<<(N + 127) / 128, 256, smem_bytes, s2>>>(x, W, N);
        cudaEventRecord(ev_join, s2);
    }

    k_zero<<<(N + T - 1) / T, T>>>(N);
    k_hist<<<(E + T - 1) / T, T>>>(ei, E);
    k_scan1<<<SCAN_BLOCKS, SCAN_BS>>>(N);
    k_scan2<<<1, 256>>>();
    k_scan3<<<(N + T - 1) / T, T>>>(N);
    k_bucket<<<(E + T - 1) / T, T>>>(ei, E);

    if (fork) {
        cudaStreamWaitEvent(0, ev_join, 0);
    } else {
        k_gemm_mma<<<(N + 127) / 128, 256, smem_bytes>>>(x, W, N);
    }

    k_accum<<<(N + 7) / 8, 256>>>(b, out, N);
}

// round 9
// speedup vs baseline: 3.2803x; 1.0218x over previous
#include <cuda_runtime.h>
#include <cuda_fp16.h>
#include <stdint.h>

// ---------------------------------------------------------------------------
// GCNConv on GB300 (sm_103a, compute_103 PTX target -> mma.sync tf32x3 GEMM)
//   CSR counting-sort aggregation (no fp32 atomics); GEMM overlapped with CSR
//   build via fork/join streams; xlin stored fp16 to halve gather traffic.
// edge_index is int32 on device (JAX x64 disabled).
// ---------------------------------------------------------------------------

#define NMAX 100000
#define EMAX 1600000
#define DIM  128
#define SCAN_BS 512
#define SCAN_BLOCKS ((NMAX + SCAN_BS - 1) / SCAN_BS)   // 196

__device__ int    g_cnt [NMAX];
__device__ int    g_start[NMAX];
__device__ int    g_cur [NMAX];
__device__ float  g_dinv[NMAX];
__device__ int    g_bsum[SCAN_BLOCKS];
__device__ int    g_scantmp[NMAX];
__device__ int    g_esrc[EMAX];
__device__ __half g_xlin_h[(size_t)NMAX * DIM];

// ----------------------------- histogram -----------------------------------
__global__ void k_zero(int N) {
    int i = blockIdx.x * blockDim.x + threadIdx.x;
    if (i < N) g_cnt[i] = 0;
}
__global__ void k_hist(const int* __restrict__ ei, int E) {
    int e = blockIdx.x * blockDim.x + threadIdx.x;
    if (e < E) atomicAdd(&g_cnt[ei[E + e]], 1);
}

// ------------------------- 3-pass scan (+dinv fused) -------------------------
__global__ void k_scan1(int N) {
    __shared__ int sm[SCAN_BS];
    int i = blockIdx.x * SCAN_BS + threadIdx.x;
    int v = (i < N) ? g_cnt[i] : 0;
    if (i < N) g_dinv[i] = rsqrtf((float)(v + 1));   // fused dinv
    sm[threadIdx.x] = v;
    __syncthreads();
#pragma unroll
    for (int ofs = 1; ofs < SCAN_BS; ofs <<= 1) {
        int t = (threadIdx.x >= ofs) ? sm[threadIdx.x - ofs] : 0;
        __syncthreads();
        sm[threadIdx.x] += t;
        __syncthreads();
    }
    if (i < N) g_scantmp[i] = sm[threadIdx.x] - v;
    if (threadIdx.x == SCAN_BS - 1) g_bsum[blockIdx.x] = sm[threadIdx.x];
}
__global__ void k_scan2() {
    __shared__ int sm[256];
    int v = (threadIdx.x < SCAN_BLOCKS) ? g_bsum[threadIdx.x] : 0;
    sm[threadIdx.x] = v;
    __syncthreads();
#pragma unroll
    for (int ofs = 1; ofs < 256; ofs <<= 1) {
        int t = (threadIdx.x >= ofs) ? sm[threadIdx.x - ofs] : 0;
        __syncthreads();
        sm[threadIdx.x] += t;
        __syncthreads();
    }
    if (threadIdx.x < SCAN_BLOCKS) g_bsum[threadIdx.x] = sm[threadIdx.x] - v;
}
__global__ void k_scan3(int N) {
    int i = blockIdx.x * blockDim.x + threadIdx.x;
    if (i < N) {
        int s = g_scantmp[i] + g_bsum[i / SCAN_BS];
        g_start[i] = s;
        g_cur[i] = s;
    }
}
__global__ void k_bucket(const int* __restrict__ ei, int E) {
    int e = blockIdx.x * blockDim.x + threadIdx.x;
    if (e < E) {
        int s = ei[e];
        int d = ei[E + e];
        g_esrc[atomicAdd(&g_cur[d], 1)] = s;
    }
}

// ------------------------- mma.sync TF32x3 GEMM ------------------------------
// xlin[n][o] = sum_k x[n][k] * W[o][k]; result stored as fp16.
// CTA: 128 rows x 128 cols; 8 warps = 4 row-groups(32) x 2 col-groups(64).
// K in 2 chunks of 64; raw f32 staged in smem; hi/lo tf32 split in registers.

#define PA 68      // xs row pitch: bank = 4*tg + tq -> conflict free
#define PW 136     // ws row pitch: bank = 8*tq + tg -> conflict free
#define XS 0                       // 128*68 floats
#define WS (128 * PA)              // 64*136 floats
#define SM_FLOATS (128 * PA + 64 * PW)   // 17408 floats = 69632 B

__device__ __forceinline__ float tf32_rna(float v) {
    uint32_t r;
    asm("cvt.rna.tf32.f32 %0, %1;" : "=r"(r) : "f"(v));
    return __uint_as_float(r);
}

__device__ __forceinline__ void mma_tf32(float c[4], uint32_t a0, uint32_t a1,
                                         uint32_t a2, uint32_t a3,
                                         uint32_t b0, uint32_t b1) {
    asm volatile(
        "mma.sync.aligned.m16n8k8.row.col.f32.tf32.tf32.f32 "
        "{%0,%1,%2,%3}, {%4,%5,%6,%7}, {%8,%9}, {%0,%1,%2,%3};"
        : "+f"(c[0]), "+f"(c[1]), "+f"(c[2]), "+f"(c[3])
        : "r"(a0), "r"(a1), "r"(a2), "r"(a3), "r"(b0), "r"(b1));
}

__global__ void __launch_bounds__(256) k_gemm_mma(const float* __restrict__ x,
                                                  const float* __restrict__ W, int N) {
    extern __shared__ float sm[];
    int t = threadIdx.x;
    int lane = t & 31, w = t >> 5;
    int tg = lane >> 2, tq = lane & 3;
    int mwarp = (w >> 1) * 32;   // 0,32,64,96
    int nwarp = (w & 1) * 64;    // 0,64
    int row0 = blockIdx.x * 128;

    const float4* x4 = reinterpret_cast<const float4*>(x);
    const float4* W4 = reinterpret_cast<const float4*>(W);

    float acc[2][8][4];
#pragma unroll
    for (int mt = 0; mt < 2; mt++)
#pragma unroll
        for (int nt = 0; nt < 8; nt++)
#pragma unroll
            for (int c = 0; c < 4; c++) acc[mt][nt][c] = 0.f;

    for (int kc = 0; kc < 2; kc++) {
        // stage x chunk raw: 128 rows x 64 k = 2048 float4 (8/thread)
        for (int i = t; i < 2048; i += 256) {
            int r = i >> 4, q = i & 15;
            int gr = row0 + r;
            float4 v = (gr < N) ? x4[(size_t)gr * 32 + kc * 16 + q]
                                : make_float4(0.f, 0.f, 0.f, 0.f);
            *reinterpret_cast<float4*>(&sm[XS + r * PA + q * 4]) = v;
        }
        // stage W chunk transposed raw: ws[k][o] = W[o][kc*64+k]
        for (int i = t; i < 2048; i += 256) {
            int o = i & 127, q = i >> 7;      // q: 0..15 -> k = 4q..4q+3
            float4 v = W4[(size_t)o * 32 + kc * 16 + q];
            sm[WS + (q * 4 + 0) * PW + o] = v.x;
            sm[WS + (q * 4 + 1) * PW + o] = v.y;
            sm[WS + (q * 4 + 2) * PW + o] = v.z;
            sm[WS + (q * 4 + 3) * PW + o] = v.w;
        }
        __syncthreads();

#pragma unroll
        for (int ks = 0; ks < 8; ks++) {
            int kb = ks * 8;
            uint32_t ahi[2][4], alo[2][4];
#pragma unroll
            for (int mt = 0; mt < 2; mt++) {
                int mrow = mwarp + mt * 16 + tg;
                float ar[4];
                ar[0] = sm[XS + (mrow    ) * PA + kb + tq];
                ar[1] = sm[XS + (mrow + 8) * PA + kb + tq];
                ar[2] = sm[XS + (mrow    ) * PA + kb + tq + 4];
                ar[3] = sm[XS + (mrow + 8) * PA + kb + tq + 4];
#pragma unroll
                for (int j = 0; j < 4; j++) {
                    float hi = tf32_rna(ar[j]);
                    ahi[mt][j] = __float_as_uint(hi);
                    alo[mt][j] = __float_as_uint(ar[j] - hi);
                }
            }
#pragma unroll
            for (int nt = 0; nt < 8; nt++) {
                int o = nwarp + nt * 8 + tg;
                float b0r = sm[WS + (kb + tq    ) * PW + o];
                float b1r = sm[WS + (kb + tq + 4) * PW + o];
                float bh0 = tf32_rna(b0r), bh1 = tf32_rna(b1r);
                uint32_t bhi0 = __float_as_uint(bh0);
                uint32_t bhi1 = __float_as_uint(bh1);
                uint32_t blo0 = __float_as_uint(b0r - bh0);
                uint32_t blo1 = __float_as_uint(b1r - bh1);
#pragma unroll
                for (int mt = 0; mt < 2; mt++) {
                    mma_tf32(acc[mt][nt], ahi[mt][0], ahi[mt][1], ahi[mt][2], ahi[mt][3], bhi0, bhi1);
                    mma_tf32(acc[mt][nt], ahi[mt][0], ahi[mt][1], ahi[mt][2], ahi[mt][3], blo0, blo1);
                    mma_tf32(acc[mt][nt], alo[mt][0], alo[mt][1], alo[mt][2], alo[mt][3], bhi0, bhi1);
                }
            }
        }
        __syncthreads();
    }

    // epilogue: fp16 stores (half2 per 2 cols)
#pragma unroll
    for (int mt = 0; mt < 2; mt++) {
        int gr = row0 + mwarp + mt * 16 + tg;
#pragma unroll
        for (int nt = 0; nt < 8; nt++) {
            int gc = nwarp + nt * 8 + tq * 2;
            if (gr < N)
                *reinterpret_cast<__half2*>(&g_xlin_h[(size_t)gr * DIM + gc]) =
                    __floats2half2_rn(acc[mt][nt][0], acc[mt][nt][1]);
            if (gr + 8 < N)
                *reinterpret_cast<__half2*>(&g_xlin_h[(size_t)(gr + 8) * DIM + gc]) =
                    __floats2half2_rn(acc[mt][nt][2], acc[mt][nt][3]);
        }
    }
}

// ------------------------- gather + accumulate -------------------------------
// One warp per dst; lane covers 4 cols (8 B fp16 per gather -> 256 B per row).
__device__ __forceinline__ float4 ld_row_h(int row, int lane) {
    const uint2* p = reinterpret_cast<const uint2*>(
        g_xlin_h + (size_t)row * DIM + lane * 4);
    uint2 u = *p;
    __half2 h0 = *reinterpret_cast<__half2*>(&u.x);
    __half2 h1 = *reinterpret_cast<__half2*>(&u.y);
    float2 f0 = __half22float2(h0), f1 = __half22float2(h1);
    return make_float4(f0.x, f0.y, f1.x, f1.y);
}

__global__ void k_accum(const float* __restrict__ b, float* __restrict__ out, int N) {
    int d = blockIdx.x * 8 + (threadIdx.x >> 5);
    int lane = threadIdx.x & 31;
    if (d >= N) return;

    float dd = g_dinv[d];
    int start = g_start[d];
    int cnt = g_cnt[d];

    float4 bb = reinterpret_cast<const float4*>(b)[lane];
    float4 sv = ld_row_h(d, lane);
    float s2 = dd * dd;
    float4 acc;
    acc.x = bb.x + sv.x * s2;
    acc.y = bb.y + sv.y * s2;
    acc.z = bb.z + sv.z * s2;
    acc.w = bb.w + sv.w * s2;

    for (int base = 0; base < cnt; base += 32) {
        int k = base + lane;
        int s = (k < cnt) ? g_esrc[start + k] : 0;
        float nm = (k < cnt) ? g_dinv[s] * dd : 0.f;
        int m = min(32, cnt - base);
        for (int j = 0; j < m; j++) {
            int sj = __shfl_sync(0xffffffffu, s, j);
            float nj = __shfl_sync(0xffffffffu, nm, j);
            float4 v = ld_row_h(sj, lane);
            acc.x += v.x * nj;
            acc.y += v.y * nj;
            acc.z += v.z * nj;
            acc.w += v.w * nj;
        }
    }

    reinterpret_cast<float4*>(out)[(size_t)d * 32 + lane] = acc;
}

// ------------------------------- launcher ------------------------------------
extern "C" void kernel_launch(void* const* d_in, const int* in_sizes, int n_in,
                              void* d_out, int out_size) {
    const float* x  = (const float*)d_in[0];
    const int*   ei = (const int*)d_in[1];   // int32 (JAX x64 disabled)
    const float* W  = (const float*)d_in[2];
    const float* b  = (const float*)d_in[3];
    float*       out = (float*)d_out;

    int N = in_sizes[0] / DIM;   // 100000
    int E = in_sizes[1] / 2;     // 1600000

    // one-time stream/event setup (first call is the uncaptured correctness run)
    static cudaStream_t s2 = 0;
    static cudaEvent_t ev_fork = 0, ev_join = 0;
    static bool init_done = false;
    if (!init_done) {
        if (cudaStreamCreateWithFlags(&s2, cudaStreamNonBlocking) != cudaSuccess) s2 = 0;
        cudaEventCreateWithFlags(&ev_fork, cudaEventDisableTiming);
        cudaEventCreateWithFlags(&ev_join, cudaEventDisableTiming);
        init_done = true;
    }

    const int T = 256;
    int smem_bytes = SM_FLOATS * sizeof(float);   // 69632
    cudaFuncSetAttribute(k_gemm_mma, cudaFuncAttributeMaxDynamicSharedMemorySize, smem_bytes);

    bool fork = (s2 != 0) && ev_fork && ev_join;

    if (fork) {
        cudaEventRecord(ev_fork, 0);
        cudaStreamWaitEvent(s2, ev_fork, 0);
        k_gemm_mma<<<(N + 127) / 128, 256, smem_bytes, s2>>>(x, W, N);
        cudaEventRecord(ev_join, s2);
    }

    k_zero<<<(N + T - 1) / T, T>>>(N);
    k_hist<<<(E + T - 1) / T, T>>>(ei, E);
    k_scan1<<<SCAN_BLOCKS, SCAN_BS>>>(N);
    k_scan2<<<1, 256>>>();
    k_scan3<<<(N + T - 1) / T, T>>>(N);
    k_bucket<<<(E + T - 1) / T, T>>>(ei, E);

    if (fork) {
        cudaStreamWaitEvent(0, ev_join, 0);
    } else {
        k_gemm_mma<<<(N + 127) / 128, 256, smem_bytes>>>(x, W, N);
    }

    k_accum<<<(N + 7) / 8, 256>>>(b, out, N);
}

// round 10
// speedup vs baseline: 3.4744x; 1.0592x over previous
#include <cuda_runtime.h>
#include <cuda_fp16.h>
#include <stdint.h>

// ---------------------------------------------------------------------------
// GCNConv on GB300 (sm_103a, compute_103 PTX target -> mma.sync tf32x3 GEMM)
//   CSR counting-sort aggregation; GEMM overlapped with CSR build (fork/join);
//   xlin stored fp16; MLP-optimized gather (4 edges in flight per warp).
// edge_index is int32 on device (JAX x64 disabled).
// ---------------------------------------------------------------------------

#define NMAX 100000
#define EMAX 1600000
#define DIM  128
#define SCAN_BS 512
#define SCAN_BLOCKS ((NMAX + SCAN_BS - 1) / SCAN_BS)   // 196

__device__ int    g_cnt [NMAX];
__device__ int    g_start[NMAX];
__device__ int    g_cur [NMAX];
__device__ float  g_dinv[NMAX];
__device__ int    g_bsum[SCAN_BLOCKS];
__device__ int    g_scantmp[NMAX];
__device__ int    g_esrc[EMAX];
__device__ __half g_xlin_h[(size_t)NMAX * DIM];

// ----------------------------- histogram -----------------------------------
__global__ void k_zero(int N) {
    int i = blockIdx.x * blockDim.x + threadIdx.x;
    if (i < N) g_cnt[i] = 0;
}
__global__ void k_hist(const int* __restrict__ ei, int E) {
    int e = blockIdx.x * blockDim.x + threadIdx.x;
    if (e < E) atomicAdd(&g_cnt[ei[E + e]], 1);
}

// ------------------------- 3-pass scan (+dinv fused) -------------------------
__global__ void k_scan1(int N) {
    __shared__ int sm[SCAN_BS];
    int i = blockIdx.x * SCAN_BS + threadIdx.x;
    int v = (i < N) ? g_cnt[i] : 0;
    if (i < N) g_dinv[i] = rsqrtf((float)(v + 1));
    sm[threadIdx.x] = v;
    __syncthreads();
#pragma unroll
    for (int ofs = 1; ofs < SCAN_BS; ofs <<= 1) {
        int t = (threadIdx.x >= ofs) ? sm[threadIdx.x - ofs] : 0;
        __syncthreads();
        sm[threadIdx.x] += t;
        __syncthreads();
    }
    if (i < N) g_scantmp[i] = sm[threadIdx.x] - v;
    if (threadIdx.x == SCAN_BS - 1) g_bsum[blockIdx.x] = sm[threadIdx.x];
}
__global__ void k_scan2() {
    __shared__ int sm[256];
    int v = (threadIdx.x < SCAN_BLOCKS) ? g_bsum[threadIdx.x] : 0;
    sm[threadIdx.x] = v;
    __syncthreads();
#pragma unroll
    for (int ofs = 1; ofs < 256; ofs <<= 1) {
        int t = (threadIdx.x >= ofs) ? sm[threadIdx.x - ofs] : 0;
        __syncthreads();
        sm[threadIdx.x] += t;
        __syncthreads();
    }
    if (threadIdx.x < SCAN_BLOCKS) g_bsum[threadIdx.x] = sm[threadIdx.x] - v;
}
__global__ void k_scan3(int N) {
    int i = blockIdx.x * blockDim.x + threadIdx.x;
    if (i < N) {
        int s = g_scantmp[i] + g_bsum[i / SCAN_BS];
        g_start[i] = s;
        g_cur[i] = s;
    }
}
__global__ void k_bucket(const int* __restrict__ ei, int E) {
    int e = blockIdx.x * blockDim.x + threadIdx.x;
    if (e < E) {
        int s = ei[e];
        int d = ei[E + e];
        g_esrc[atomicAdd(&g_cur[d], 1)] = s;
    }
}

// ------------------------- mma.sync TF32x3 GEMM ------------------------------
#define PA 68
#define PW 136
#define XS 0
#define WS (128 * PA)
#define SM_FLOATS (128 * PA + 64 * PW)   // 69632 B

__device__ __forceinline__ float tf32_rna(float v) {
    uint32_t r;
    asm("cvt.rna.tf32.f32 %0, %1;" : "=r"(r) : "f"(v));
    return __uint_as_float(r);
}

__device__ __forceinline__ void mma_tf32(float c[4], uint32_t a0, uint32_t a1,
                                         uint32_t a2, uint32_t a3,
                                         uint32_t b0, uint32_t b1) {
    asm volatile(
        "mma.sync.aligned.m16n8k8.row.col.f32.tf32.tf32.f32 "
        "{%0,%1,%2,%3}, {%4,%5,%6,%7}, {%8,%9}, {%0,%1,%2,%3};"
        : "+f"(c[0]), "+f"(c[1]), "+f"(c[2]), "+f"(c[3])
        : "r"(a0), "r"(a1), "r"(a2), "r"(a3), "r"(b0), "r"(b1));
}

__global__ void __launch_bounds__(256) k_gemm_mma(const float* __restrict__ x,
                                                  const float* __restrict__ W, int N) {
    extern __shared__ float sm[];
    int t = threadIdx.x;
    int lane = t & 31, w = t >> 5;
    int tg = lane >> 2, tq = lane & 3;
    int mwarp = (w >> 1) * 32;
    int nwarp = (w & 1) * 64;
    int row0 = blockIdx.x * 128;

    const float4* x4 = reinterpret_cast<const float4*>(x);
    const float4* W4 = reinterpret_cast<const float4*>(W);

    float acc[2][8][4];
#pragma unroll
    for (int mt = 0; mt < 2; mt++)
#pragma unroll
        for (int nt = 0; nt < 8; nt++)
#pragma unroll
            for (int c = 0; c < 4; c++) acc[mt][nt][c] = 0.f;

    for (int kc = 0; kc < 2; kc++) {
        for (int i = t; i < 2048; i += 256) {
            int r = i >> 4, q = i & 15;
            int gr = row0 + r;
            float4 v = (gr < N) ? x4[(size_t)gr * 32 + kc * 16 + q]
                                : make_float4(0.f, 0.f, 0.f, 0.f);
            *reinterpret_cast<float4*>(&sm[XS + r * PA + q * 4]) = v;
        }
        for (int i = t; i < 2048; i += 256) {
            int o = i & 127, q = i >> 7;
            float4 v = W4[(size_t)o * 32 + kc * 16 + q];
            sm[WS + (q * 4 + 0) * PW + o] = v.x;
            sm[WS + (q * 4 + 1) * PW + o] = v.y;
            sm[WS + (q * 4 + 2) * PW + o] = v.z;
            sm[WS + (q * 4 + 3) * PW + o] = v.w;
        }
        __syncthreads();

#pragma unroll
        for (int ks = 0; ks < 8; ks++) {
            int kb = ks * 8;
            uint32_t ahi[2][4], alo[2][4];
#pragma unroll
            for (int mt = 0; mt < 2; mt++) {
                int mrow = mwarp + mt * 16 + tg;
                float ar[4];
                ar[0] = sm[XS + (mrow    ) * PA + kb + tq];
                ar[1] = sm[XS + (mrow + 8) * PA + kb + tq];
                ar[2] = sm[XS + (mrow    ) * PA + kb + tq + 4];
                ar[3] = sm[XS + (mrow + 8) * PA + kb + tq + 4];
#pragma unroll
                for (int j = 0; j < 4; j++) {
                    float hi = tf32_rna(ar[j]);
                    ahi[mt][j] = __float_as_uint(hi);
                    alo[mt][j] = __float_as_uint(ar[j] - hi);
                }
            }
#pragma unroll
            for (int nt = 0; nt < 8; nt++) {
                int o = nwarp + nt * 8 + tg;
                float b0r = sm[WS + (kb + tq    ) * PW + o];
                float b1r = sm[WS + (kb + tq + 4) * PW + o];
                float bh0 = tf32_rna(b0r), bh1 = tf32_rna(b1r);
                uint32_t bhi0 = __float_as_uint(bh0);
                uint32_t bhi1 = __float_as_uint(bh1);
                uint32_t blo0 = __float_as_uint(b0r - bh0);
                uint32_t blo1 = __float_as_uint(b1r - bh1);
#pragma unroll
                for (int mt = 0; mt < 2; mt++) {
                    mma_tf32(acc[mt][nt], ahi[mt][0], ahi[mt][1], ahi[mt][2], ahi[mt][3], bhi0, bhi1);
                    mma_tf32(acc[mt][nt], ahi[mt][0], ahi[mt][1], ahi[mt][2], ahi[mt][3], blo0, blo1);
                    mma_tf32(acc[mt][nt], alo[mt][0], alo[mt][1], alo[mt][2], alo[mt][3], bhi0, bhi1);
                }
            }
        }
        __syncthreads();
    }

#pragma unroll
    for (int mt = 0; mt < 2; mt++) {
        int gr = row0 + mwarp + mt * 16 + tg;
#pragma unroll
        for (int nt = 0; nt < 8; nt++) {
            int gc = nwarp + nt * 8 + tq * 2;
            if (gr < N)
                *reinterpret_cast<__half2*>(&g_xlin_h[(size_t)gr * DIM + gc]) =
                    __floats2half2_rn(acc[mt][nt][0], acc[mt][nt][1]);
            if (gr + 8 < N)
                *reinterpret_cast<__half2*>(&g_xlin_h[(size_t)(gr + 8) * DIM + gc]) =
                    __floats2half2_rn(acc[mt][nt][2], acc[mt][nt][3]);
        }
    }
}

// ------------------------- gather + accumulate (MLP x4) ----------------------
// One warp per dst. 4 groups of 8 lanes; lane covers 16 fp16 cols (2x uint4);
// each loop step processes 4 edges -> 8 LDG.128 in flight per warp.
__device__ __forceinline__ void fma16(float acc[16], uint4 u0, uint4 u1, float n) {
    const uint32_t* pu = &u0.x;
#pragma unroll
    for (int q = 0; q < 4; q++) {
        float2 f = __half22float2(*reinterpret_cast<const __half2*>(&pu[q]));
        acc[q * 2 + 0] += f.x * n;
        acc[q * 2 + 1] += f.y * n;
    }
    const uint32_t* pv = &u1.x;
#pragma unroll
    for (int q = 0; q < 4; q++) {
        float2 f = __half22float2(*reinterpret_cast<const __half2*>(&pv[q]));
        acc[8 + q * 2 + 0] += f.x * n;
        acc[8 + q * 2 + 1] += f.y * n;
    }
}

__global__ void k_accum(const float* __restrict__ bias, float* __restrict__ out, int N) {
    int d = blockIdx.x * 8 + (threadIdx.x >> 5);
    int lane = threadIdx.x & 31;
    if (d >= N) return;
    int g = lane >> 3, li = lane & 7;

    float dd = g_dinv[d];
    int start = g_start[d];
    int cnt = g_cnt[d];

    float acc[16];
#pragma unroll
    for (int c = 0; c < 16; c++) acc[c] = 0.f;

    // group 0 seeds bias + self-loop
    if (g == 0) {
        float s2 = dd * dd;
        const uint4* sp = reinterpret_cast<const uint4*>(g_xlin_h + (size_t)d * DIM + li * 16);
        uint4 u0 = sp[0], u1 = sp[1];
        fma16(acc, u0, u1, s2);
#pragma unroll
        for (int q = 0; q < 4; q++) {
            float4 bv = reinterpret_cast<const float4*>(bias)[li * 4 + q];
            acc[q * 4 + 0] += bv.x;
            acc[q * 4 + 1] += bv.y;
            acc[q * 4 + 2] += bv.z;
            acc[q * 4 + 3] += bv.w;
        }
    }

    for (int base = 0; base < cnt; base += 32) {
        int k = base + lane;
        int s = (k < cnt) ? g_esrc[start + k] : 0;
        float nm = (k < cnt) ? g_dinv[s] * dd : 0.f;
        int m = min(32, cnt - base);
        for (int j = 0; j < m; j += 4) {
            int idx = (j + g) & 31;
            int sj = __shfl_sync(0xffffffffu, s, idx);
            float nj = __shfl_sync(0xffffffffu, nm, idx);
            if (j + g >= m) { sj = d; nj = 0.f; }   // safe dummy gather
            const uint4* p = reinterpret_cast<const uint4*>(
                g_xlin_h + (size_t)sj * DIM + li * 16);
            uint4 u0 = p[0], u1 = p[1];
            fma16(acc, u0, u1, nj);
        }
    }

    // reduce the 4 group partials
#pragma unroll
    for (int c = 0; c < 16; c++) {
        acc[c] += __shfl_xor_sync(0xffffffffu, acc[c], 8);
        acc[c] += __shfl_xor_sync(0xffffffffu, acc[c], 16);
    }

    if (g == 0) {
        float4* o4 = reinterpret_cast<float4*>(out + (size_t)d * DIM + li * 16);
#pragma unroll
        for (int q = 0; q < 4; q++)
            o4[q] = make_float4(acc[q * 4 + 0], acc[q * 4 + 1],
                                acc[q * 4 + 2], acc[q * 4 + 3]);
    }
}

// ------------------------------- launcher ------------------------------------
extern "C" void kernel_launch(void* const* d_in, const int* in_sizes, int n_in,
                              void* d_out, int out_size) {
    const float* x  = (const float*)d_in[0];
    const int*   ei = (const int*)d_in[1];
    const float* W  = (const float*)d_in[2];
    const float* b  = (const float*)d_in[3];
    float*       out = (float*)d_out;

    int N = in_sizes[0] / DIM;   // 100000
    int E = in_sizes[1] / 2;     // 1600000

    static cudaStream_t s2 = 0;
    static cudaEvent_t ev_fork = 0, ev_join = 0;
    static bool init_done = false;
    if (!init_done) {
        if (cudaStreamCreateWithFlags(&s2, cudaStreamNonBlocking) != cudaSuccess) s2 = 0;
        cudaEventCreateWithFlags(&ev_fork, cudaEventDisableTiming);
        cudaEventCreateWithFlags(&ev_join, cudaEventDisableTiming);
        init_done = true;
    }

    const int T = 256;
    int smem_bytes = SM_FLOATS * sizeof(float);
    cudaFuncSetAttribute(k_gemm_mma, cudaFuncAttributeMaxDynamicSharedMemorySize, smem_bytes);

    bool fork = (s2 != 0) && ev_fork && ev_join;

    if (fork) {
        cudaEventRecord(ev_fork, 0);
        cudaStreamWaitEvent(s2, ev_fork, 0);
        k_gemm_mma<<<(N + 127) / 128, 256, smem_bytes, s2>>>(x, W, N);
        cudaEventRecord(ev_join, s2);
    }

    k_zero<<<(N + T - 1) / T, T>>>(N);
    k_hist<<<(E + T - 1) / T, T>>>(ei, E);
    k_scan1<<<SCAN_BLOCKS, SCAN_BS>>>(N);
    k_scan2<<<1, 256>>>();
    k_scan3<<<(N + T - 1) / T, T>>>(N);
    k_bucket<<<(E + T - 1) / T, T>>>(ei, E);

    if (fork) {
        cudaStreamWaitEvent(0, ev_join, 0);
    } else {
        k_gemm_mma<<<(N + 127) / 128, 256, smem_bytes>>>(x, W, N);
    }

    k_accum<<<(N + 7) / 8, 256>>>(b, out, N);
}

// round 11
// speedup vs baseline: 3.5304x; 1.0161x over previous
#include <cuda_runtime.h>
#include <cuda_fp16.h>
#include <stdint.h>

// ---------------------------------------------------------------------------
// GCNConv on GB300 (sm_103a, compute_103 PTX target -> mma.sync tf32x3 GEMM)
//   CSR counting-sort aggregation; GEMM overlapped with CSR build (fork/join);
//   xlin stored fp16; edge records carry premultiplied norm; MLP-unrolled
//   gather-accumulate.
// edge_index is int32 on device (JAX x64 disabled).
// ---------------------------------------------------------------------------

#define NMAX 100000
#define EMAX 1600000
#define DIM  128
#define SCAN_BS 512
#define SCAN_BLOCKS ((NMAX + SCAN_BS - 1) / SCAN_BS)   // 196

__device__ int    g_cnt [NMAX];
__device__ int    g_start[NMAX];
__device__ int    g_cur [NMAX];
__device__ float  g_dinv[NMAX];
__device__ int    g_bsum[SCAN_BLOCKS];
__device__ int    g_scantmp[NMAX];
__device__ int2   g_edge[EMAX];            // {src, __float_as_int(norm)}
__device__ __half g_xlin_h[(size_t)NMAX * DIM];

// ----------------------------- histogram -----------------------------------
__global__ void k_hist(const int* __restrict__ ei, int E) {
    int e = blockIdx.x * blockDim.x + threadIdx.x;
    if (e < E) atomicAdd(&g_cnt[ei[E + e]], 1);
}

// ------------------------- 3-pass scan (+dinv fused) -------------------------
__global__ void k_scan1(int N) {
    __shared__ int sm[SCAN_BS];
    int i = blockIdx.x * SCAN_BS + threadIdx.x;
    int v = (i < N) ? g_cnt[i] : 0;
    if (i < N) g_dinv[i] = rsqrtf((float)(v + 1));
    sm[threadIdx.x] = v;
    __syncthreads();
#pragma unroll
    for (int ofs = 1; ofs < SCAN_BS; ofs <<= 1) {
        int t = (threadIdx.x >= ofs) ? sm[threadIdx.x - ofs] : 0;
        __syncthreads();
        sm[threadIdx.x] += t;
        __syncthreads();
    }
    if (i < N) g_scantmp[i] = sm[threadIdx.x] - v;
    if (threadIdx.x == SCAN_BS - 1) g_bsum[blockIdx.x] = sm[threadIdx.x];
}
__global__ void k_scan2() {
    __shared__ int sm[256];
    int v = (threadIdx.x < SCAN_BLOCKS) ? g_bsum[threadIdx.x] : 0;
    sm[threadIdx.x] = v;
    __syncthreads();
#pragma unroll
    for (int ofs = 1; ofs < 256; ofs <<= 1) {
        int t = (threadIdx.x >= ofs) ? sm[threadIdx.x - ofs] : 0;
        __syncthreads();
        sm[threadIdx.x] += t;
        __syncthreads();
    }
    if (threadIdx.x < SCAN_BLOCKS) g_bsum[threadIdx.x] = sm[threadIdx.x] - v;
}
__global__ void k_scan3(int N) {
    int i = blockIdx.x * blockDim.x + threadIdx.x;
    if (i < N) {
        int s = g_scantmp[i] + g_bsum[i / SCAN_BS];
        g_start[i] = s;
        g_cur[i] = s;
    }
}
__global__ void k_bucket(const int* __restrict__ ei, int E) {
    int e = blockIdx.x * blockDim.x + threadIdx.x;
    if (e < E) {
        int s = ei[e];
        int d = ei[E + e];
        float nm = g_dinv[s] * g_dinv[d];            // premultiplied norm
        int pos = atomicAdd(&g_cur[d], 1);
        g_edge[pos] = make_int2(s, __float_as_int(nm));
    }
}

// ------------------------- mma.sync TF32x3 GEMM ------------------------------
#define PA 68
#define PW 136
#define XS 0
#define WS (128 * PA)
#define SM_FLOATS (128 * PA + 64 * PW)   // 69632 B

__device__ __forceinline__ float tf32_rna(float v) {
    uint32_t r;
    asm("cvt.rna.tf32.f32 %0, %1;" : "=r"(r) : "f"(v));
    return __uint_as_float(r);
}

__device__ __forceinline__ void mma_tf32(float c[4], uint32_t a0, uint32_t a1,
                                         uint32_t a2, uint32_t a3,
                                         uint32_t b0, uint32_t b1) {
    asm volatile(
        "mma.sync.aligned.m16n8k8.row.col.f32.tf32.tf32.f32 "
        "{%0,%1,%2,%3}, {%4,%5,%6,%7}, {%8,%9}, {%0,%1,%2,%3};"
        : "+f"(c[0]), "+f"(c[1]), "+f"(c[2]), "+f"(c[3])
        : "r"(a0), "r"(a1), "r"(a2), "r"(a3), "r"(b0), "r"(b1));
}

__global__ void __launch_bounds__(256) k_gemm_mma(const float* __restrict__ x,
                                                  const float* __restrict__ W, int N) {
    extern __shared__ float sm[];
    int t = threadIdx.x;
    int lane = t & 31, w = t >> 5;
    int tg = lane >> 2, tq = lane & 3;
    int mwarp = (w >> 1) * 32;
    int nwarp = (w & 1) * 64;
    int row0 = blockIdx.x * 128;

    const float4* x4 = reinterpret_cast<const float4*>(x);
    const float4* W4 = reinterpret_cast<const float4*>(W);

    float acc[2][8][4];
#pragma unroll
    for (int mt = 0; mt < 2; mt++)
#pragma unroll
        for (int nt = 0; nt < 8; nt++)
#pragma unroll
            for (int c = 0; c < 4; c++) acc[mt][nt][c] = 0.f;

    for (int kc = 0; kc < 2; kc++) {
        for (int i = t; i < 2048; i += 256) {
            int r = i >> 4, q = i & 15;
            int gr = row0 + r;
            float4 v = (gr < N) ? x4[(size_t)gr * 32 + kc * 16 + q]
                                : make_float4(0.f, 0.f, 0.f, 0.f);
            *reinterpret_cast<float4*>(&sm[XS + r * PA + q * 4]) = v;
        }
        for (int i = t; i < 2048; i += 256) {
            int o = i & 127, q = i >> 7;
            float4 v = W4[(size_t)o * 32 + kc * 16 + q];
            sm[WS + (q * 4 + 0) * PW + o] = v.x;
            sm[WS + (q * 4 + 1) * PW + o] = v.y;
            sm[WS + (q * 4 + 2) * PW + o] = v.z;
            sm[WS + (q * 4 + 3) * PW + o] = v.w;
        }
        __syncthreads();

#pragma unroll
        for (int ks = 0; ks < 8; ks++) {
            int kb = ks * 8;
            uint32_t ahi[2][4], alo[2][4];
#pragma unroll
            for (int mt = 0; mt < 2; mt++) {
                int mrow = mwarp + mt * 16 + tg;
                float ar[4];
                ar[0] = sm[XS + (mrow    ) * PA + kb + tq];
                ar[1] = sm[XS + (mrow + 8) * PA + kb + tq];
                ar[2] = sm[XS + (mrow    ) * PA + kb + tq + 4];
                ar[3] = sm[XS + (mrow + 8) * PA + kb + tq + 4];
#pragma unroll
                for (int j = 0; j < 4; j++) {
                    float hi = tf32_rna(ar[j]);
                    ahi[mt][j] = __float_as_uint(hi);
                    alo[mt][j] = __float_as_uint(ar[j] - hi);
                }
            }
#pragma unroll
            for (int nt = 0; nt < 8; nt++) {
                int o = nwarp + nt * 8 + tg;
                float b0r = sm[WS + (kb + tq    ) * PW + o];
                float b1r = sm[WS + (kb + tq + 4) * PW + o];
                float bh0 = tf32_rna(b0r), bh1 = tf32_rna(b1r);
                uint32_t bhi0 = __float_as_uint(bh0);
                uint32_t bhi1 = __float_as_uint(bh1);
                uint32_t blo0 = __float_as_uint(b0r - bh0);
                uint32_t blo1 = __float_as_uint(b1r - bh1);
#pragma unroll
                for (int mt = 0; mt < 2; mt++) {
                    mma_tf32(acc[mt][nt], ahi[mt][0], ahi[mt][1], ahi[mt][2], ahi[mt][3], bhi0, bhi1);
                    mma_tf32(acc[mt][nt], ahi[mt][0], ahi[mt][1], ahi[mt][2], ahi[mt][3], blo0, blo1);
                    mma_tf32(acc[mt][nt], alo[mt][0], alo[mt][1], alo[mt][2], alo[mt][3], bhi0, bhi1);
                }
            }
        }
        __syncthreads();
    }

#pragma unroll
    for (int mt = 0; mt < 2; mt++) {
        int gr = row0 + mwarp + mt * 16 + tg;
#pragma unroll
        for (int nt = 0; nt < 8; nt++) {
            int gc = nwarp + nt * 8 + tq * 2;
            if (gr < N)
                *reinterpret_cast<__half2*>(&g_xlin_h[(size_t)gr * DIM + gc]) =
                    __floats2half2_rn(acc[mt][nt][0], acc[mt][nt][1]);
            if (gr + 8 < N)
                *reinterpret_cast<__half2*>(&g_xlin_h[(size_t)(gr + 8) * DIM + gc]) =
                    __floats2half2_rn(acc[mt][nt][2], acc[mt][nt][3]);
        }
    }
}

// ------------------------- gather + accumulate -------------------------------
// One warp per dst; 4 groups of 8 lanes; lane covers 16 fp16 cols (2x uint4).
// Edge records hold premultiplied norm -> no shfl, no dinv gather; unroll x2.
__device__ __forceinline__ void fma16(float acc[16], uint4 u0, uint4 u1, float n) {
    const uint32_t* pu = &u0.x;
#pragma unroll
    for (int q = 0; q < 4; q++) {
        float2 f = __half22float2(*reinterpret_cast<const __half2*>(&pu[q]));
        acc[q * 2 + 0] += f.x * n;
        acc[q * 2 + 1] += f.y * n;
    }
    const uint32_t* pv = &u1.x;
#pragma unroll
    for (int q = 0; q < 4; q++) {
        float2 f = __half22float2(*reinterpret_cast<const __half2*>(&pv[q]));
        acc[8 + q * 2 + 0] += f.x * n;
        acc[8 + q * 2 + 1] += f.y * n;
    }
}

__global__ void k_accum(const float* __restrict__ bias, float* __restrict__ out, int N) {
    int d = blockIdx.x * 8 + (threadIdx.x >> 5);
    int lane = threadIdx.x & 31;
    if (d >= N) return;
    int g = lane >> 3, li = lane & 7;

    float dd = g_dinv[d];
    int start = g_start[d];
    int cnt = g_cnt[d];

    float acc[16];
#pragma unroll
    for (int c = 0; c < 16; c++) acc[c] = 0.f;

    if (g == 0) {
        float s2 = dd * dd;
        const uint4* sp = reinterpret_cast<const uint4*>(g_xlin_h + (size_t)d * DIM + li * 16);
        uint4 u0 = sp[0], u1 = sp[1];
        fma16(acc, u0, u1, s2);
#pragma unroll
        for (int q = 0; q < 4; q++) {
            float4 bv = reinterpret_cast<const float4*>(bias)[li * 4 + q];
            acc[q * 4 + 0] += bv.x;
            acc[q * 4 + 1] += bv.y;
            acc[q * 4 + 2] += bv.z;
            acc[q * 4 + 3] += bv.w;
        }
    }

    const int2* recs = g_edge + start;
    int k = g;
    // unrolled x2: 2 records + 4 row LDG.128 in flight before first FMA
    for (; k + 4 < cnt; k += 8) {
        int2 r0 = recs[k];
        int2 r1 = recs[k + 4];
        const uint4* p0 = reinterpret_cast<const uint4*>(
            g_xlin_h + (size_t)r0.x * DIM + li * 16);
        const uint4* p1 = reinterpret_cast<const uint4*>(
            g_xlin_h + (size_t)r1.x * DIM + li * 16);
        uint4 a0 = p0[0], a1 = p0[1];
        uint4 b0 = p1[0], b1 = p1[1];
        fma16(acc, a0, a1, __int_as_float(r0.y));
        fma16(acc, b0, b1, __int_as_float(r1.y));
    }
    if (k < cnt) {
        int2 r0 = recs[k];
        const uint4* p0 = reinterpret_cast<const uint4*>(
            g_xlin_h + (size_t)r0.x * DIM + li * 16);
        uint4 a0 = p0[0], a1 = p0[1];
        fma16(acc, a0, a1, __int_as_float(r0.y));
    }

#pragma unroll
    for (int c = 0; c < 16; c++) {
        acc[c] += __shfl_xor_sync(0xffffffffu, acc[c], 8);
        acc[c] += __shfl_xor_sync(0xffffffffu, acc[c], 16);
    }

    if (g == 0) {
        float4* o4 = reinterpret_cast<float4*>(out + (size_t)d * DIM + li * 16);
#pragma unroll
        for (int q = 0; q < 4; q++)
            o4[q] = make_float4(acc[q * 4 + 0], acc[q * 4 + 1],
                                acc[q * 4 + 2], acc[q * 4 + 3]);
    }
}

// ------------------------------- launcher ------------------------------------
extern "C" void kernel_launch(void* const* d_in, const int* in_sizes, int n_in,
                              void* d_out, int out_size) {
    const float* x  = (const float*)d_in[0];
    const int*   ei = (const int*)d_in[1];
    const float* W  = (const float*)d_in[2];
    const float* b  = (const float*)d_in[3];
    float*       out = (float*)d_out;

    int N = in_sizes[0] / DIM;   // 100000
    int E = in_sizes[1] / 2;     // 1600000

    static cudaStream_t s2 = 0;
    static cudaEvent_t ev_fork = 0, ev_join = 0;
    static void* cnt_addr = 0;
    static bool init_done = false;
    if (!init_done) {
        if (cudaStreamCreateWithFlags(&s2, cudaStreamNonBlocking) != cudaSuccess) s2 = 0;
        cudaEventCreateWithFlags(&ev_fork, cudaEventDisableTiming);
        cudaEventCreateWithFlags(&ev_join, cudaEventDisableTiming);
        cudaGetSymbolAddress(&cnt_addr, g_cnt);
        init_done = true;
    }

    const int T = 256;
    int smem_bytes = SM_FLOATS * sizeof(float);
    cudaFuncSetAttribute(k_gemm_mma, cudaFuncAttributeMaxDynamicSharedMemorySize, smem_bytes);

    bool fork = (s2 != 0) && ev_fork && ev_join;

    if (fork) {
        cudaEventRecord(ev_fork, 0);
        cudaStreamWaitEvent(s2, ev_fork, 0);
        k_gemm_mma<<<(N + 127) / 128, 256, smem_bytes, s2>>>(x, W, N);
        cudaEventRecord(ev_join, s2);
    }

    cudaMemsetAsync(cnt_addr, 0, (size_t)N * sizeof(int), 0);
    k_hist<<<(E + T - 1) / T, T>>>(ei, E);
    k_scan1<<<SCAN_BLOCKS, SCAN_BS>>>(N);
    k_scan2<<<1, 256>>>();
    k_scan3<<<(N + T - 1) / T, T>>>(N);
    k_bucket<<<(E + T - 1) / T, T>>>(ei, E);

    if (fork) {
        cudaStreamWaitEvent(0, ev_join, 0);
    } else {
        k_gemm_mma<<<(N + 127) / 128, 256, smem_bytes>>>(x, W, N);
    }

    k_accum<<<(N + 7) / 8, 256>>>(b, out, N);
}

// round 12
// speedup vs baseline: 4.0130x; 1.1367x over previous
#include <cuda_runtime.h>
#include <cuda_fp16.h>
#include <stdint.h>

// ---------------------------------------------------------------------------
// GCNConv on GB300 (sm_103a, compute_103 PTX target)
//   CSR counting-sort aggregation; single-pass TF32 mma.sync GEMM (11-bit
//   mantissa ~ fp16 storage precision already in use); GEMM overlapped with
//   CSR build (fork/join); xlin fp16; edge records carry premultiplied norm.
// edge_index is int32 on device (JAX x64 disabled).
// ---------------------------------------------------------------------------

#define NMAX 100000
#define EMAX 1600000
#define DIM  128
#define SCAN_BS 512
#define SCAN_BLOCKS ((NMAX + SCAN_BS - 1) / SCAN_BS)   // 196

__device__ int    g_cnt [NMAX];
__device__ int    g_start[NMAX];
__device__ int    g_cur [NMAX];
__device__ float  g_dinv[NMAX];
__device__ int    g_bsum[SCAN_BLOCKS];
__device__ int    g_scantmp[NMAX];
__device__ int2   g_edge[EMAX];            // {src, __float_as_int(norm)}
__device__ __half g_xlin_h[(size_t)NMAX * DIM];

// ----------------------------- histogram -----------------------------------
__global__ void k_hist(const int* __restrict__ ei, int E) {
    int e = blockIdx.x * blockDim.x + threadIdx.x;
    if (e < E) atomicAdd(&g_cnt[ei[E + e]], 1);
}

// ------------------------- scan pass 1 (+dinv fused) -------------------------
__global__ void k_scan1(int N) {
    __shared__ int sm[SCAN_BS];
    int i = blockIdx.x * SCAN_BS + threadIdx.x;
    int v = (i < N) ? g_cnt[i] : 0;
    if (i < N) g_dinv[i] = rsqrtf((float)(v + 1));
    sm[threadIdx.x] = v;
    __syncthreads();
#pragma unroll
    for (int ofs = 1; ofs < SCAN_BS; ofs <<= 1) {
        int t = (threadIdx.x >= ofs) ? sm[threadIdx.x - ofs] : 0;
        __syncthreads();
        sm[threadIdx.x] += t;
        __syncthreads();
    }
    if (i < N) g_scantmp[i] = sm[threadIdx.x] - v;
    if (threadIdx.x == SCAN_BS - 1) g_bsum[blockIdx.x] = sm[threadIdx.x];
}

// --------------- scan pass 2: per-block bsum reduction + finalize -------------
// 256-thread blocks over N; block b covers a slice of exactly one 512-scan
// block (sb = b>>1), so the needed prefix is a reduction over g_bsum[0..sb).
__global__ void k_scan3(int N) {
    int t = threadIdx.x;
    int i = blockIdx.x * 256 + t;
    int sb = blockIdx.x >> 1;

    int v = (t < sb) ? g_bsum[t] : 0;   // SCAN_BLOCKS=196 <= 256
#pragma unroll
    for (int o = 16; o > 0; o >>= 1) v += __shfl_down_sync(0xffffffffu, v, o);
    __shared__ int wsum[8];
    if ((t & 31) == 0) wsum[t >> 5] = v;
    __syncthreads();
    __shared__ int pre_s;
    if (t < 8) {
        int s = wsum[t];
#pragma unroll
        for (int o = 4; o > 0; o >>= 1) s += __shfl_down_sync(0x000000ffu, s, o);
        if (t == 0) pre_s = s;
    }
    __syncthreads();

    if (i < N) {
        int s = g_scantmp[i] + pre_s;
        g_start[i] = s;
        g_cur[i] = s;
    }
}

__global__ void k_bucket(const int* __restrict__ ei, int E) {
    int e = blockIdx.x * blockDim.x + threadIdx.x;
    if (e < E) {
        int s = ei[e];
        int d = ei[E + e];
        float nm = g_dinv[s] * g_dinv[d];
        int pos = atomicAdd(&g_cur[d], 1);
        g_edge[pos] = make_int2(s, __float_as_int(nm));
    }
}

// ------------------------- mma.sync TF32 GEMM (single pass) ------------------
#define PA 68
#define PW 136
#define XS 0
#define WS (128 * PA)
#define SM_FLOATS (128 * PA + 64 * PW)   // 69632 B

__device__ __forceinline__ uint32_t tf32_of(float v) {
    uint32_t r;
    asm("cvt.rna.tf32.f32 %0, %1;" : "=r"(r) : "f"(v));
    return r;
}

__device__ __forceinline__ void mma_tf32(float c[4], uint32_t a0, uint32_t a1,
                                         uint32_t a2, uint32_t a3,
                                         uint32_t b0, uint32_t b1) {
    asm volatile(
        "mma.sync.aligned.m16n8k8.row.col.f32.tf32.tf32.f32 "
        "{%0,%1,%2,%3}, {%4,%5,%6,%7}, {%8,%9}, {%0,%1,%2,%3};"
        : "+f"(c[0]), "+f"(c[1]), "+f"(c[2]), "+f"(c[3])
        : "r"(a0), "r"(a1), "r"(a2), "r"(a3), "r"(b0), "r"(b1));
}

__global__ void __launch_bounds__(256) k_gemm_mma(const float* __restrict__ x,
                                                  const float* __restrict__ W, int N) {
    extern __shared__ float sm[];
    int t = threadIdx.x;
    int lane = t & 31, w = t >> 5;
    int tg = lane >> 2, tq = lane & 3;
    int mwarp = (w >> 1) * 32;
    int nwarp = (w & 1) * 64;
    int row0 = blockIdx.x * 128;

    const float4* x4 = reinterpret_cast<const float4*>(x);
    const float4* W4 = reinterpret_cast<const float4*>(W);

    float acc[2][8][4];
#pragma unroll
    for (int mt = 0; mt < 2; mt++)
#pragma unroll
        for (int nt = 0; nt < 8; nt++)
#pragma unroll
            for (int c = 0; c < 4; c++) acc[mt][nt][c] = 0.f;

    for (int kc = 0; kc < 2; kc++) {
        for (int i = t; i < 2048; i += 256) {
            int r = i >> 4, q = i & 15;
            int gr = row0 + r;
            float4 v = (gr < N) ? x4[(size_t)gr * 32 + kc * 16 + q]
                                : make_float4(0.f, 0.f, 0.f, 0.f);
            *reinterpret_cast<float4*>(&sm[XS + r * PA + q * 4]) = v;
        }
        for (int i = t; i < 2048; i += 256) {
            int o = i & 127, q = i >> 7;
            float4 v = W4[(size_t)o * 32 + kc * 16 + q];
            sm[WS + (q * 4 + 0) * PW + o] = v.x;
            sm[WS + (q * 4 + 1) * PW + o] = v.y;
            sm[WS + (q * 4 + 2) * PW + o] = v.z;
            sm[WS + (q * 4 + 3) * PW + o] = v.w;
        }
        __syncthreads();

#pragma unroll
        for (int ks = 0; ks < 8; ks++) {
            int kb = ks * 8;
            uint32_t a[2][4];
#pragma unroll
            for (int mt = 0; mt < 2; mt++) {
                int mrow = mwarp + mt * 16 + tg;
                a[mt][0] = tf32_of(sm[XS + (mrow    ) * PA + kb + tq]);
                a[mt][1] = tf32_of(sm[XS + (mrow + 8) * PA + kb + tq]);
                a[mt][2] = tf32_of(sm[XS + (mrow    ) * PA + kb + tq + 4]);
                a[mt][3] = tf32_of(sm[XS + (mrow + 8) * PA + kb + tq + 4]);
            }
#pragma unroll
            for (int nt = 0; nt < 8; nt++) {
                int o = nwarp + nt * 8 + tg;
                uint32_t b0 = tf32_of(sm[WS + (kb + tq    ) * PW + o]);
                uint32_t b1 = tf32_of(sm[WS + (kb + tq + 4) * PW + o]);
#pragma unroll
                for (int mt = 0; mt < 2; mt++)
                    mma_tf32(acc[mt][nt], a[mt][0], a[mt][1], a[mt][2], a[mt][3], b0, b1);
            }
        }
        __syncthreads();
    }

#pragma unroll
    for (int mt = 0; mt < 2; mt++) {
        int gr = row0 + mwarp + mt * 16 + tg;
#pragma unroll
        for (int nt = 0; nt < 8; nt++) {
            int gc = nwarp + nt * 8 + tq * 2;
            if (gr < N)
                *reinterpret_cast<__half2*>(&g_xlin_h[(size_t)gr * DIM + gc]) =
                    __floats2half2_rn(acc[mt][nt][0], acc[mt][nt][1]);
            if (gr + 8 < N)
                *reinterpret_cast<__half2*>(&g_xlin_h[(size_t)(gr + 8) * DIM + gc]) =
                    __floats2half2_rn(acc[mt][nt][2], acc[mt][nt][3]);
        }
    }
}

// ------------------------- gather + accumulate -------------------------------
__device__ __forceinline__ void fma16(float acc[16], uint4 u0, uint4 u1, float n) {
    const uint32_t* pu = &u0.x;
#pragma unroll
    for (int q = 0; q < 4; q++) {
        float2 f = __half22float2(*reinterpret_cast<const __half2*>(&pu[q]));
        acc[q * 2 + 0] += f.x * n;
        acc[q * 2 + 1] += f.y * n;
    }
    const uint32_t* pv = &u1.x;
#pragma unroll
    for (int q = 0; q < 4; q++) {
        float2 f = __half22float2(*reinterpret_cast<const __half2*>(&pv[q]));
        acc[8 + q * 2 + 0] += f.x * n;
        acc[8 + q * 2 + 1] += f.y * n;
    }
}

__global__ void k_accum(const float* __restrict__ bias, float* __restrict__ out, int N) {
    int d = blockIdx.x * 8 + (threadIdx.x >> 5);
    int lane = threadIdx.x & 31;
    if (d >= N) return;
    int g = lane >> 3, li = lane & 7;

    float dd = g_dinv[d];
    int start = g_start[d];
    int cnt = g_cnt[d];

    float acc[16];
#pragma unroll
    for (int c = 0; c < 16; c++) acc[c] = 0.f;

    if (g == 0) {
        float s2 = dd * dd;
        const uint4* sp = reinterpret_cast<const uint4*>(g_xlin_h + (size_t)d * DIM + li * 16);
        uint4 u0 = sp[0], u1 = sp[1];
        fma16(acc, u0, u1, s2);
#pragma unroll
        for (int q = 0; q < 4; q++) {
            float4 bv = reinterpret_cast<const float4*>(bias)[li * 4 + q];
            acc[q * 4 + 0] += bv.x;
            acc[q * 4 + 1] += bv.y;
            acc[q * 4 + 2] += bv.z;
            acc[q * 4 + 3] += bv.w;
        }
    }

    const int2* recs = g_edge + start;
    int k = g;
    for (; k + 4 < cnt; k += 8) {
        int2 r0 = recs[k];
        int2 r1 = recs[k + 4];
        const uint4* p0 = reinterpret_cast<const uint4*>(
            g_xlin_h + (size_t)r0.x * DIM + li * 16);
        const uint4* p1 = reinterpret_cast<const uint4*>(
            g_xlin_h + (size_t)r1.x * DIM + li * 16);
        uint4 a0 = p0[0], a1 = p0[1];
        uint4 b0 = p1[0], b1 = p1[1];
        fma16(acc, a0, a1, __int_as_float(r0.y));
        fma16(acc, b0, b1, __int_as_float(r1.y));
    }
    if (k < cnt) {
        int2 r0 = recs[k];
        const uint4* p0 = reinterpret_cast<const uint4*>(
            g_xlin_h + (size_t)r0.x * DIM + li * 16);
        uint4 a0 = p0[0], a1 = p0[1];
        fma16(acc, a0, a1, __int_as_float(r0.y));
    }

#pragma unroll
    for (int c = 0; c < 16; c++) {
        acc[c] += __shfl_xor_sync(0xffffffffu, acc[c], 8);
        acc[c] += __shfl_xor_sync(0xffffffffu, acc[c], 16);
    }

    if (g == 0) {
        float4* o4 = reinterpret_cast<float4*>(out + (size_t)d * DIM + li * 16);
#pragma unroll
        for (int q = 0; q < 4; q++)
            o4[q] = make_float4(acc[q * 4 + 0], acc[q * 4 + 1],
                                acc[q * 4 + 2], acc[q * 4 + 3]);
    }
}

// ------------------------------- launcher ------------------------------------
extern "C" void kernel_launch(void* const* d_in, const int* in_sizes, int n_in,
                              void* d_out, int out_size) {
    const float* x  = (const float*)d_in[0];
    const int*   ei = (const int*)d_in[1];
    const float* W  = (const float*)d_in[2];
    const float* b  = (const float*)d_in[3];
    float*       out = (float*)d_out;

    int N = in_sizes[0] / DIM;   // 100000
    int E = in_sizes[1] / 2;     // 1600000

    static cudaStream_t s2 = 0;
    static cudaEvent_t ev_fork = 0, ev_join = 0;
    static void* cnt_addr = 0;
    static bool init_done = false;
    if (!init_done) {
        if (cudaStreamCreateWithFlags(&s2, cudaStreamNonBlocking) != cudaSuccess) s2 = 0;
        cudaEventCreateWithFlags(&ev_fork, cudaEventDisableTiming);
        cudaEventCreateWithFlags(&ev_join, cudaEventDisableTiming);
        cudaGetSymbolAddress(&cnt_addr, g_cnt);
        init_done = true;
    }

    const int T = 256;
    int smem_bytes = SM_FLOATS * sizeof(float);
    cudaFuncSetAttribute(k_gemm_mma, cudaFuncAttributeMaxDynamicSharedMemorySize, smem_bytes);

    bool fork = (s2 != 0) && ev_fork && ev_join;

    if (fork) {
        cudaEventRecord(ev_fork, 0);
        cudaStreamWaitEvent(s2, ev_fork, 0);
        k_gemm_mma<<<(N + 127) / 128, 256, smem_bytes, s2>>>(x, W, N);
        cudaEventRecord(ev_join, s2);
    }

    cudaMemsetAsync(cnt_addr, 0, (size_t)N * sizeof(int), 0);
    k_hist<<<(E + T - 1) / T, T>>>(ei, E);
    k_scan1<<<SCAN_BLOCKS, SCAN_BS>>>(N);
    k_scan3<<<(N + 255) / 256, 256>>>(N);
    k_bucket<<<(E + T - 1) / T, T>>>(ei, E);

    if (fork) {
        cudaStreamWaitEvent(0, ev_join, 0);
    } else {
        k_gemm_mma<<<(N + 127) / 128, 256, smem_bytes>>>(x, W, N);
    }

    k_accum<<<(N + 7) / 8, 256>>>(b, out, N);
}